// round 13
// baseline (speedup 1.0000x reference)
#include <cuda_runtime.h>
#include <cuda_fp16.h>
#include <cstdint>
#include <math.h>

// Problem constants
#define B_  8
#define C_  256
#define H_  64
#define W_  64
#define CR_ 64
#define L_  512
#define N_  64
#define NH_ 8
#define HD_ 32
#define NTOK (L_ * N_)          // 32768
// 1/sqrt(32) * log2(e): softmax runs in the exp2 domain
#define QK_SCALE_LOG2 (0.17677669529663687f * 1.44269504088896341f)

// ---------------- scratch (device globals; no allocations allowed) -------------
__device__ float g_pooled[B_ * C_];
__device__ float g_ca[B_ * C_];
__device__ __align__(16) __half g_xw[NTOK * C_];      // gated tokens [t][c]
__device__ __align__(16) __half g_wqkv[3 * C_ * C_];
__device__ __align__(16) __half g_wout[C_ * C_];
__device__ __align__(16) __half g_q[N_ * NH_ * L_ * HD_];  // scale*log2e folded
__device__ __align__(16) __half g_k[N_ * NH_ * L_ * HD_];
__device__ __align__(16) __half g_v[N_ * NH_ * L_ * HD_];
__device__ __align__(16) __half g_ao[NTOK * C_];      // attn out [t][h*32+d]

// ---------------- PTX helpers ---------------------------------------------------
__device__ __forceinline__ uint32_t smem_u32(const void* p) {
    uint32_t a;
    asm("{ .reg .u64 t; cvta.to.shared.u64 t, %1; cvt.u32.u64 %0, t; }" : "=r"(a) : "l"(p));
    return a;
}
__device__ __forceinline__ void ldsm_x4(uint32_t& r0, uint32_t& r1, uint32_t& r2, uint32_t& r3,
                                        uint32_t addr) {
    asm volatile("ldmatrix.sync.aligned.m8n8.x4.shared.b16 {%0,%1,%2,%3}, [%4];"
                 : "=r"(r0), "=r"(r1), "=r"(r2), "=r"(r3) : "r"(addr));
}
__device__ __forceinline__ void ldsm_x4_t(uint32_t& r0, uint32_t& r1, uint32_t& r2, uint32_t& r3,
                                          uint32_t addr) {
    asm volatile("ldmatrix.sync.aligned.m8n8.x4.trans.shared.b16 {%0,%1,%2,%3}, [%4];"
                 : "=r"(r0), "=r"(r1), "=r"(r2), "=r"(r3) : "r"(addr));
}
__device__ __forceinline__ void mma_f16(float* c, const uint32_t* a, const uint32_t* b) {
    asm volatile("mma.sync.aligned.m16n8k16.row.col.f32.f16.f16.f32 "
                 "{%0,%1,%2,%3}, {%4,%5,%6,%7}, {%8,%9}, {%0,%1,%2,%3};"
                 : "+f"(c[0]), "+f"(c[1]), "+f"(c[2]), "+f"(c[3])
                 : "r"(a[0]), "r"(a[1]), "r"(a[2]), "r"(a[3]), "r"(b[0]), "r"(b[1]));
}
__device__ __forceinline__ void cp16(uint32_t saddr, const void* g) {
    asm volatile("cp.async.cg.shared.global [%0], [%1], 16;" :: "r"(saddr), "l"(g));
}
#define CP_COMMIT() asm volatile("cp.async.commit_group;" ::: "memory")
#define CP_WAIT0()  asm volatile("cp.async.wait_group 0;" ::: "memory")
#define CP_WAIT1()  asm volatile("cp.async.wait_group 1;" ::: "memory")

#define BK 32
#define AST 40   // padded smem row stride in halfs (80B: conflict-free ldmatrix)

// f32 exp2 on MUFU
__device__ __forceinline__ float ex2(float x) {
    float r;
    asm("ex2.approx.f32 %0, %1;" : "=f"(r) : "f"(x));
    return r;
}
// packed half2 exp2 on MUFU
__device__ __forceinline__ uint32_t ex2h2(uint32_t x) {
    uint32_t r;
    asm("ex2.approx.f16x2 %0, %1;" : "=r"(r) : "r"(x));
    return r;
}
__device__ __forceinline__ uint32_t cvt2h(float lo, float hi) {
    uint32_t d;
    asm("cvt.rn.f16x2.f32 %0, %1, %2;" : "=r"(d) : "f"(hi), "f"(lo));
    return d;
}
__device__ __forceinline__ uint32_t hadd2_(uint32_t a, uint32_t b) {
    uint32_t d;
    asm("add.rn.f16x2 %0, %1, %2;" : "=r"(d) : "r"(a), "r"(b));
    return d;
}
__device__ __forceinline__ uint32_t pkh2(float a, float b) {
    __half2 t = __floats2half2_rn(a, b);
    return *reinterpret_cast<uint32_t*>(&t);
}

// ---------------- 1) merged prep: pool (blocks 0..2047) + W convert -------------
__global__ void prep_kernel(const float* __restrict__ x,
                            const float* __restrict__ in_w, const float* __restrict__ out_w) {
    int bid = blockIdx.x;
    if (bid < B_ * C_) {
        const float* p = x + (size_t)bid * (H_ * W_);
        float s = 0.f;
        for (int i = threadIdx.x; i < H_ * W_; i += 256) s += p[i];
        __shared__ float red[8];
        for (int o = 16; o; o >>= 1) s += __shfl_xor_sync(0xffffffffu, s, o);
        if ((threadIdx.x & 31) == 0) red[threadIdx.x >> 5] = s;
        __syncthreads();
        if (threadIdx.x < 8) {
            s = red[threadIdx.x];
            for (int o = 4; o; o >>= 1) s += __shfl_xor_sync(0xffu, s, o);
            if (threadIdx.x == 0) g_pooled[bid] = s * (1.0f / (H_ * W_));
        }
    } else {
        int i = (bid - B_ * C_) * 256 + threadIdx.x;
        if (i < 3 * C_ * C_) g_wqkv[i] = __float2half_rn(in_w[i]);
        if (i < C_ * C_)     g_wout[i] = __float2half_rn(out_w[i]);
    }
}

// ---------------- 2) SE gate MLP -----------------------------------------------
__global__ void se_kernel(const float* __restrict__ w1, const float* __restrict__ b1,
                          const float* __restrict__ w2, const float* __restrict__ b2) {
    __shared__ float h1s[B_ * CR_];
    int tid = threadIdx.x;
    {
        int b = tid >> 6, j = tid & 63;
        float s = b1[j];
        const float* pw = w1 + j * C_;
        const float* pp = g_pooled + b * C_;
        for (int c = 0; c < C_; c++) s += pp[c] * pw[c];
        h1s[tid] = fmaxf(s, 0.f);
    }
    __syncthreads();
    for (int i = tid; i < B_ * C_; i += 512) {
        int b = i >> 8, c = i & 255;
        float s = b2[c];
        const float* pw = w2 + c * CR_;
        const float* ph = h1s + b * CR_;
        for (int j = 0; j < CR_; j++) s += ph[j] * pw[j];
        g_ca[i] = 1.0f / (1.0f + expf(-s));
    }
}

// ---------------- 3) gather gated windows into fp16 token matrix ---------------
__global__ void gather_kernel(const float* __restrict__ x) {
    int hp = blockIdx.x;
    int cg = blockIdx.y;
    int b  = blockIdx.z;
    __shared__ float tile[32][65];
    int tid = threadIdx.x;
    int wp = tid & 63, ci = tid >> 6;
    const float* base = x + (((size_t)(b * C_ + cg * 32)) << 12) + hp * W_;
#pragma unroll
    for (int i = 0; i < 8; i++) {
        int c = ci + i * 4;
        tile[c][wp] = base[((size_t)c << 12) + wp];
    }
    __syncthreads();
    int j = tid & 31, pi = tid >> 5;
    int hw = hp >> 3, r = hp & 7;
    float cav = g_ca[b * C_ + cg * 32 + j];
#pragma unroll
    for (int i = 0; i < 8; i++) {
        int wpp = pi + i * 8;
        int ww = wpp >> 3, cc = wpp & 7;
        int l = (hw * 8 + ww) * 8 + b;
        int t = l * 64 + (r * 8 + cc);
        g_xw[(size_t)t * C_ + cg * 32 + j] = __float2half_rn(tile[j][wpp] * cav);
    }
}

// ---- shared mainloop: fp16 HMMA GEMM 64x128 tile, 3 CTAs/SM, cp.async 3-stage --
// per stage: A tile 64x32 + B tile 128x32, padded to AST
#define STAGE_HALFS (192 * AST)
#define GEMM_SMEM (3 * STAGE_HALFS * 2)

__device__ __forceinline__ void gemm_load_chunk(__half* Ab, __half* Bb,
    const __half* __restrict__ A, const __half* __restrict__ Bm,
    int m0, int n0, int k0, int tid) {
    {
        int row = tid >> 2, q = tid & 3;   // 64 rows x 4 quads
        cp16(smem_u32(Ab + row * AST + q * 8), A + (size_t)(m0 + row) * C_ + k0 + q * 8);
    }
#pragma unroll
    for (int p = 0; p < 2; p++) {
        int i = tid + p * 256;
        int row = i >> 2, q = i & 3;       // 128 rows x 4 quads
        cp16(smem_u32(Bb + row * AST + q * 8), Bm + (size_t)(n0 + row) * C_ + k0 + q * 8);
    }
    CP_COMMIT();
}

// 8 warps as 2(M) x 4(N); warp tile 32 x 32; acc[mt 0..1][nt 0..3][4]
__device__ __forceinline__ void gemm_mainloop(__half* gsm,
    const __half* __restrict__ A, const __half* __restrict__ Bm,
    int m0, int n0, float acc[2][4][4]) {
    int tid = threadIdx.x;
    int lane = tid & 31, wid = tid >> 5;
    int wm = wid & 1, wn = wid >> 1;
    int lrow = lane & 15, lkq = lane >> 4;

    __half* Ab[3] = { gsm, gsm + STAGE_HALFS, gsm + 2 * STAGE_HALFS };
#define BB(s) (Ab[s] + 64 * AST)

    gemm_load_chunk(Ab[0], BB(0), A, Bm, m0, n0, 0, tid);
    gemm_load_chunk(Ab[1], BB(1), A, Bm, m0, n0, BK, tid);

    for (int chunk = 0; chunk < 8; chunk++) {
        int buf = chunk - (chunk >= 6 ? 6 : (chunk >= 3 ? 3 : 0));   // chunk % 3
        if (chunk < 7) CP_WAIT1(); else CP_WAIT0();
        __syncthreads();
        if (chunk < 6) {
            int nb = buf + 2 >= 3 ? buf - 1 : buf + 2;               // (chunk+2) % 3
            gemm_load_chunk(Ab[nb], BB(nb), A, Bm, m0, n0, (chunk + 2) * BK, tid);
        }

        uint32_t sA0 = smem_u32(Ab[buf]);
        uint32_t sB0 = smem_u32(BB(buf));
#pragma unroll
        for (int ks = 0; ks < 2; ks++) {
            int kk = ks * 16 + lkq * 8;
            uint32_t a4[2][4], bA[4], bB[4];
#pragma unroll
            for (int mt = 0; mt < 2; mt++) {
                int row = wm * 32 + mt * 16 + lrow;
                ldsm_x4(a4[mt][0], a4[mt][1], a4[mt][2], a4[mt][3],
                        sA0 + (uint32_t)(row * AST + kk) * 2);
            }
            ldsm_x4(bA[0], bA[1], bA[2], bA[3],
                    sB0 + (uint32_t)((wn * 32 + lrow) * AST + kk) * 2);
            ldsm_x4(bB[0], bB[1], bB[2], bB[3],
                    sB0 + (uint32_t)((wn * 32 + 16 + lrow) * AST + kk) * 2);
            uint32_t b0[2] = { bA[0], bA[2] }, b1[2] = { bA[1], bA[3] };
            uint32_t b2[2] = { bB[0], bB[2] }, b3[2] = { bB[1], bB[3] };
#pragma unroll
            for (int mt = 0; mt < 2; mt++) {
                mma_f16(acc[mt][0], a4[mt], b0);
                mma_f16(acc[mt][1], a4[mt], b1);
                mma_f16(acc[mt][2], a4[mt], b2);
                mma_f16(acc[mt][3], a4[mt], b3);
            }
        }
    }
#undef BB
}

// ---------------- 4) QKV projection (fp16 HMMA) --------------------------------
__global__ __launch_bounds__(256, 3) void qkv_mma_kernel(const float* __restrict__ bias) {
    extern __shared__ __half gsm[];
    int m0 = blockIdx.x * 64;
    int n0 = blockIdx.y * 128;
    float acc[2][4][4];
#pragma unroll
    for (int mt = 0; mt < 2; mt++)
#pragma unroll
        for (int nt = 0; nt < 4; nt++)
#pragma unroll
            for (int j = 0; j < 4; j++) acc[mt][nt][j] = 0.f;

    gemm_mainloop(gsm, g_xw, g_wqkv, m0, n0, acc);

    int lane = threadIdx.x & 31, wid = threadIdx.x >> 5;
    int wm = wid & 1, wn = wid >> 1;
    int sec = n0 >> 8;                 // 0=Q, 1=K, 2=V
    __half* dst = (sec == 0) ? g_q : (sec == 1) ? g_k : g_v;
    float scale = (sec == 0) ? QK_SCALE_LOG2 : 1.0f;
    int l = m0 >> 6;                   // block spans exactly one l (64 tokens)
    int r = lane >> 2;
#pragma unroll
    for (int mt = 0; mt < 2; mt++) {
#pragma unroll
        for (int nt = 0; nt < 4; nt++) {
            int col = n0 + wn * 32 + nt * 8 + (lane & 3) * 2;
            int oc = col & 255;
            int h = oc >> 5, d = oc & 31;
            float2 bi = *(const float2*)&bias[col];
#pragma unroll
            for (int half = 0; half < 2; half++) {
                int n = wm * 32 + mt * 16 + r + half * 8;
                float v0 = (acc[mt][nt][half * 2 + 0] + bi.x) * scale;
                float v1 = (acc[mt][nt][half * 2 + 1] + bi.y) * scale;
                size_t idx = (((size_t)(n * NH_ + h) * L_ + l) << 5) + d;
                *(uint32_t*)(dst + idx) = pkh2(v0, v1);
            }
        }
    }
}

// ---------------- 5) attention (fp16 HMMA flash, f16x2 softmax) ----------------
__device__ __forceinline__ void attn_compute_S(float s[8][4], const uint32_t aq[2][4],
                                               uint32_t sK, int lrow, int lkq) {
#pragma unroll
    for (int j = 0; j < 8; j++)
#pragma unroll
        for (int c = 0; c < 4; c++) s[j][c] = 0.f;
#pragma unroll
    for (int ks = 0; ks < 2; ks++) {
        int kk = ks * 16 + lkq * 8;
#pragma unroll
        for (int j = 0; j < 4; j++) {
            uint32_t b4[4];
            ldsm_x4(b4[0], b4[1], b4[2], b4[3],
                    sK + (uint32_t)((j * 16 + lrow) * AST + kk) * 2);
            uint32_t b0[2] = { b4[0], b4[2] }, b1[2] = { b4[1], b4[3] };
            mma_f16(s[2 * j + 0], aq[ks], b0);
            mma_f16(s[2 * j + 1], aq[ks], b1);
        }
    }
}

__global__ __launch_bounds__(256, 2) void attn_mma_kernel() {
    int qt = blockIdx.x;   // 0..3
    int h  = blockIdx.y;   // 0..7
    int n  = blockIdx.z;   // 0..63
    __shared__ __half Qs[128][AST];
    __shared__ __half Ks[2][64][AST];
    __shared__ __half Vs[2][64][AST];

    size_t head = ((size_t)(n * NH_ + h)) * L_ * HD_;
    const __half* qg = g_q + head;
    const __half* kg = g_k + head;
    const __half* vg = g_v + head;

    int tid = threadIdx.x;
    int lane = tid & 31, wid = tid >> 5;
    int kvrow = tid >> 2, kvq = tid & 3;
    int lrow = lane & 15, lkq = lane >> 4;

    // prologue: K0+V0 (group), K1 (group), Q plain
    {
        size_t gi = (size_t)kvrow * HD_ + kvq * 8;
        cp16(smem_u32(&Ks[0][kvrow][kvq * 8]), kg + gi);
        cp16(smem_u32(&Vs[0][kvrow][kvq * 8]), vg + gi);
        CP_COMMIT();
        cp16(smem_u32(&Ks[1][kvrow][kvq * 8]), kg + (size_t)(64 + kvrow) * HD_ + kvq * 8);
        CP_COMMIT();
    }
#pragma unroll
    for (int p = 0; p < 2; p++) {
        int i = tid + p * 256;
        int row = i >> 2, q = i & 3;
        *(uint4*)&Qs[row][q * 8] = *(const uint4*)(qg + (size_t)(qt * 128 + row) * HD_ + q * 8);
    }
    uint32_t sQ = smem_u32(&Qs[0][0]);

    CP_WAIT0();
    __syncthreads();

    // hoisted persistent Q fragments (warp rows [wid*16, wid*16+16))
    uint32_t aq[2][4];
#pragma unroll
    for (int ks = 0; ks < 2; ks++)
        ldsm_x4(aq[ks][0], aq[ks][1], aq[ks][2], aq[ks][3],
                sQ + (uint32_t)((wid * 16 + lrow) * AST + ks * 16 + lkq * 8) * 2);

    float s[2][8][4];
    attn_compute_S(s[0], aq, smem_u32(&Ks[0][0][0]), lrow, lkq);
    __syncthreads();   // protect Ks[0] from kt=0's K2 prefetch overwrite

    float o[4][4];
#pragma unroll
    for (int i = 0; i < 4; i++)
#pragma unroll
        for (int j = 0; j < 4; j++) o[i][j] = 0.f;
    float mrow[2] = { -1e30f, -1e30f };
    float lsum[2] = { 0.f, 0.f };

#pragma unroll 2
    for (int kt = 0; kt < 8; kt++) {
        const int cur = kt & 1, nxt = cur ^ 1;
        // prefetch K(kt+2) -> Ks[cur] (K(kt) is dead), V(kt+1) -> Vs[nxt]
        if (kt < 6)
            cp16(smem_u32(&Ks[cur][kvrow][kvq * 8]),
                 kg + (size_t)((kt + 2) * 64 + kvrow) * HD_ + kvq * 8);
        if (kt < 7) {
            cp16(smem_u32(&Vs[nxt][kvrow][kvq * 8]),
                 vg + (size_t)((kt + 1) * 64 + kvrow) * HD_ + kvq * 8);
            CP_COMMIT();
            attn_compute_S(s[nxt], aq, smem_u32(&Ks[nxt][0][0]), lrow, lkq);
        }

        // ---- online softmax on s[cur] -> packed-half P fragments directly ----
        float (*sc)[4] = s[cur];
        float mx0 = -1e30f, mx1 = -1e30f;
#pragma unroll
        for (int j = 0; j < 8; j++) {
            mx0 = fmaxf(mx0, fmaxf(sc[j][0], sc[j][1]));
            mx1 = fmaxf(mx1, fmaxf(sc[j][2], sc[j][3]));
        }
        mx0 = fmaxf(mx0, __shfl_xor_sync(0xffffffffu, mx0, 1));
        mx0 = fmaxf(mx0, __shfl_xor_sync(0xffffffffu, mx0, 2));
        mx1 = fmaxf(mx1, __shfl_xor_sync(0xffffffffu, mx1, 1));
        mx1 = fmaxf(mx1, __shfl_xor_sync(0xffffffffu, mx1, 2));
        float mn0 = fmaxf(mrow[0], mx0), mn1 = fmaxf(mrow[1], mx1);
        float al0 = ex2(mrow[0] - mn0), al1 = ex2(mrow[1] - mn1);

        uint32_t ap[4][4];
        uint32_t hs0 = 0, hs1 = 0;   // packed half2 partial row sums
#pragma unroll
        for (int ks = 0; ks < 4; ks++) {
            int j0 = 2 * ks, j1 = 2 * ks + 1;
            uint32_t p00 = ex2h2(cvt2h(sc[j0][0] - mn0, sc[j0][1] - mn0));
            uint32_t p01 = ex2h2(cvt2h(sc[j0][2] - mn1, sc[j0][3] - mn1));
            uint32_t p10 = ex2h2(cvt2h(sc[j1][0] - mn0, sc[j1][1] - mn0));
            uint32_t p11 = ex2h2(cvt2h(sc[j1][2] - mn1, sc[j1][3] - mn1));
            ap[ks][0] = p00; ap[ks][1] = p01; ap[ks][2] = p10; ap[ks][3] = p11;
            hs0 = hadd2_(hadd2_(hs0, p00), p10);
            hs1 = hadd2_(hadd2_(hs1, p01), p11);
        }
        {
            float2 f0 = __half22float2(*(const __half2*)&hs0);
            float2 f1 = __half22float2(*(const __half2*)&hs1);
            lsum[0] = lsum[0] * al0 + f0.x + f0.y;
            lsum[1] = lsum[1] * al1 + f1.x + f1.y;
        }
        mrow[0] = mn0; mrow[1] = mn1;
#pragma unroll
        for (int nt = 0; nt < 4; nt++) {
            o[nt][0] *= al0; o[nt][1] *= al0;
            o[nt][2] *= al1; o[nt][3] *= al1;
        }

        // ---- O += P V ----
        uint32_t sV = smem_u32(&Vs[cur][0][0]);
#pragma unroll
        for (int ks = 0; ks < 4; ks++) {
#pragma unroll
            for (int half = 0; half < 2; half++) {
                uint32_t v4[4];
                ldsm_x4_t(v4[0], v4[1], v4[2], v4[3],
                          sV + (uint32_t)((ks * 16 + lrow) * AST + half * 16 + lkq * 8) * 2);
                uint32_t bv0[2] = { v4[0], v4[1] }, bv1[2] = { v4[2], v4[3] };
                mma_f16(o[half * 2 + 0], ap[ks], bv0);
                mma_f16(o[half * 2 + 1], ap[ks], bv1);
            }
        }
        if (kt < 7) {
            CP_WAIT0();
            __syncthreads();
        }
    }

    // ---- epilogue: final lsum reduction + write ao ----
    lsum[0] += __shfl_xor_sync(0xffffffffu, lsum[0], 1);
    lsum[0] += __shfl_xor_sync(0xffffffffu, lsum[0], 2);
    lsum[1] += __shfl_xor_sync(0xffffffffu, lsum[1], 1);
    lsum[1] += __shfl_xor_sync(0xffffffffu, lsum[1], 2);
    int r = lane >> 2, cp = (lane & 3) * 2;
#pragma unroll
    for (int half = 0; half < 2; half++) {
        int row = wid * 16 + r + half * 8;
        int l = qt * 128 + row;
        float inv = 1.0f / lsum[half];
        size_t base = ((size_t)(l * 64 + n)) * C_ + h * 32;
#pragma unroll
        for (int nt = 0; nt < 4; nt++) {
            float v0 = o[nt][half * 2 + 0] * inv;
            float v1 = o[nt][half * 2 + 1] * inv;
            *(uint32_t*)(g_ao + base + nt * 8 + cp) = pkh2(v0, v1);
        }
    }
}

// ---------------- 6) out-proj (fp16 HMMA) + gated residual ---------------------
__global__ __launch_bounds__(256, 3) void outproj_mma_kernel(const float* __restrict__ bias,
                                                             const float* __restrict__ x,
                                                             float* __restrict__ out) {
    extern __shared__ __half gsm[];
    int m0 = blockIdx.x * 64;
    int n0 = blockIdx.y * 128;
    float acc[2][4][4];
#pragma unroll
    for (int mt = 0; mt < 2; mt++)
#pragma unroll
        for (int nt = 0; nt < 4; nt++)
#pragma unroll
            for (int j = 0; j < 4; j++) acc[mt][nt][j] = 0.f;

    gemm_mainloop(gsm, g_ao, g_wout, m0, n0, acc);

    int lane = threadIdx.x & 31, wid = threadIdx.x >> 5;
    int wm = wid & 1, wn = wid >> 1;
    int l = m0 >> 6;
    int win = l >> 3, b = l & 7;
    int r = lane >> 2;
#pragma unroll
    for (int mt = 0; mt < 2; mt++) {
#pragma unroll
        for (int nt = 0; nt < 4; nt++) {
            int col = n0 + wn * 32 + nt * 8 + (lane & 3) * 2;
            float2 bi = *(const float2*)&bias[col];
            float ca0 = g_ca[b * C_ + col];
            float ca1 = g_ca[b * C_ + col + 1];
#pragma unroll
            for (int half = 0; half < 2; half++) {
                int wq = wm * 32 + mt * 16 + r + half * 8;
                size_t idx0 = (((size_t)(b * C_ + col)) * H_ + win) * W_ + wq;
                size_t idx1 = idx0 + (size_t)H_ * W_;
                out[idx0] = x[idx0] * ca0 + acc[mt][nt][half * 2 + 0] + bi.x;
                out[idx1] = x[idx1] * ca1 + acc[mt][nt][half * 2 + 1] + bi.y;
            }
        }
    }
}

// ---------------- launch --------------------------------------------------------
extern "C" void kernel_launch(void* const* d_in, const int* in_sizes, int n_in,
                              void* d_out, int out_size) {
    const float* x     = (const float*)d_in[0];
    const float* ca_w1 = (const float*)d_in[1];
    const float* ca_b1 = (const float*)d_in[2];
    const float* ca_w2 = (const float*)d_in[3];
    const float* ca_b2 = (const float*)d_in[4];
    const float* in_w  = (const float*)d_in[5];
    const float* in_b  = (const float*)d_in[6];
    const float* out_w = (const float*)d_in[7];
    const float* out_b = (const float*)d_in[8];
    float* out = (float*)d_out;

    cudaFuncSetAttribute(qkv_mma_kernel, cudaFuncAttributeMaxDynamicSharedMemorySize, GEMM_SMEM);
    cudaFuncSetAttribute(outproj_mma_kernel, cudaFuncAttributeMaxDynamicSharedMemorySize, GEMM_SMEM);

    int conv_blocks = (3 * C_ * C_ + 255) / 256;
    prep_kernel<<<B_ * C_ + conv_blocks, 256>>>(x, in_w, out_w);
    se_kernel<<<1, 512>>>(ca_w1, ca_b1, ca_w2, ca_b2);
    gather_kernel<<<dim3(64, 8, 8), 256>>>(x);
    qkv_mma_kernel<<<dim3(NTOK / 64, 6), 256, GEMM_SMEM>>>(in_b);
    attn_mma_kernel<<<dim3(4, 8, 64), 256>>>();
    outproj_mma_kernel<<<dim3(NTOK / 64, 2), 256, GEMM_SMEM>>>(out_b, x, out);
}

// round 14
// speedup vs baseline: 1.0226x; 1.0226x over previous
#include <cuda_runtime.h>
#include <cuda_fp16.h>
#include <cstdint>
#include <math.h>

// Problem constants
#define B_  8
#define C_  256
#define H_  64
#define W_  64
#define CR_ 64
#define L_  512
#define N_  64
#define NH_ 8
#define HD_ 32
#define NTOK (L_ * N_)          // 32768
// 1/sqrt(32) * log2(e): softmax runs in the exp2 domain
#define QK_SCALE_LOG2 (0.17677669529663687f * 1.44269504088896341f)

// ---------------- scratch (device globals; no allocations allowed) -------------
__device__ float g_pooled[B_ * C_];
__device__ float g_ca[B_ * C_];
__device__ __align__(16) __half g_xw[NTOK * C_];      // gated tokens [t][c]
__device__ __align__(16) __half g_wqkv[3 * C_ * C_];
__device__ __align__(16) __half g_wout[C_ * C_];
__device__ __align__(16) __half g_q[N_ * NH_ * L_ * HD_];  // scale*log2e folded
__device__ __align__(16) __half g_k[N_ * NH_ * L_ * HD_];
__device__ __align__(16) __half g_v[N_ * NH_ * L_ * HD_];
__device__ __align__(16) __half g_ao[NTOK * C_];      // attn out [t][h*32+d]

// ---------------- PTX helpers ---------------------------------------------------
__device__ __forceinline__ uint32_t smem_u32(const void* p) {
    uint32_t a;
    asm("{ .reg .u64 t; cvta.to.shared.u64 t, %1; cvt.u32.u64 %0, t; }" : "=r"(a) : "l"(p));
    return a;
}
__device__ __forceinline__ void ldsm_x4(uint32_t& r0, uint32_t& r1, uint32_t& r2, uint32_t& r3,
                                        uint32_t addr) {
    asm volatile("ldmatrix.sync.aligned.m8n8.x4.shared.b16 {%0,%1,%2,%3}, [%4];"
                 : "=r"(r0), "=r"(r1), "=r"(r2), "=r"(r3) : "r"(addr));
}
__device__ __forceinline__ void ldsm_x4_t(uint32_t& r0, uint32_t& r1, uint32_t& r2, uint32_t& r3,
                                          uint32_t addr) {
    asm volatile("ldmatrix.sync.aligned.m8n8.x4.trans.shared.b16 {%0,%1,%2,%3}, [%4];"
                 : "=r"(r0), "=r"(r1), "=r"(r2), "=r"(r3) : "r"(addr));
}
__device__ __forceinline__ void mma_f16(float* c, const uint32_t* a, const uint32_t* b) {
    asm volatile("mma.sync.aligned.m16n8k16.row.col.f32.f16.f16.f32 "
                 "{%0,%1,%2,%3}, {%4,%5,%6,%7}, {%8,%9}, {%0,%1,%2,%3};"
                 : "+f"(c[0]), "+f"(c[1]), "+f"(c[2]), "+f"(c[3])
                 : "r"(a[0]), "r"(a[1]), "r"(a[2]), "r"(a[3]), "r"(b[0]), "r"(b[1]));
}
__device__ __forceinline__ void cp16(uint32_t saddr, const void* g) {
    asm volatile("cp.async.cg.shared.global [%0], [%1], 16;" :: "r"(saddr), "l"(g));
}
#define CP_COMMIT() asm volatile("cp.async.commit_group;" ::: "memory")
#define CP_WAIT0()  asm volatile("cp.async.wait_group 0;" ::: "memory")
#define CP_WAIT1()  asm volatile("cp.async.wait_group 1;" ::: "memory")
#define CP_WAIT2()  asm volatile("cp.async.wait_group 2;" ::: "memory")

#define BK 32
#define AST 40   // padded smem row stride in halfs (80B: conflict-free ldmatrix)

// f32 exp2 on MUFU
__device__ __forceinline__ float ex2(float x) {
    float r;
    asm("ex2.approx.f32 %0, %1;" : "=f"(r) : "f"(x));
    return r;
}
// packed half2 exp2 on MUFU
__device__ __forceinline__ uint32_t ex2h2(uint32_t x) {
    uint32_t r;
    asm("ex2.approx.f16x2 %0, %1;" : "=r"(r) : "r"(x));
    return r;
}
__device__ __forceinline__ uint32_t cvt2h(float lo, float hi) {
    uint32_t d;
    asm("cvt.rn.f16x2.f32 %0, %1, %2;" : "=r"(d) : "f"(hi), "f"(lo));
    return d;
}
__device__ __forceinline__ uint32_t hadd2_(uint32_t a, uint32_t b) {
    uint32_t d;
    asm("add.rn.f16x2 %0, %1, %2;" : "=r"(d) : "r"(a), "r"(b));
    return d;
}
__device__ __forceinline__ uint32_t pkh2(float a, float b) {
    __half2 t = __floats2half2_rn(a, b);
    return *reinterpret_cast<uint32_t*>(&t);
}

// ---------------- 1) merged prep: pool (blocks 0..2047) + W convert -------------
__global__ void prep_kernel(const float* __restrict__ x,
                            const float* __restrict__ in_w, const float* __restrict__ out_w) {
    int bid = blockIdx.x;
    if (bid < B_ * C_) {
        const float* p = x + (size_t)bid * (H_ * W_);
        float s = 0.f;
        for (int i = threadIdx.x; i < H_ * W_; i += 256) s += p[i];
        __shared__ float red[8];
        for (int o = 16; o; o >>= 1) s += __shfl_xor_sync(0xffffffffu, s, o);
        if ((threadIdx.x & 31) == 0) red[threadIdx.x >> 5] = s;
        __syncthreads();
        if (threadIdx.x < 8) {
            s = red[threadIdx.x];
            for (int o = 4; o; o >>= 1) s += __shfl_xor_sync(0xffu, s, o);
            if (threadIdx.x == 0) g_pooled[bid] = s * (1.0f / (H_ * W_));
        }
    } else {
        int i = (bid - B_ * C_) * 256 + threadIdx.x;
        if (i < 3 * C_ * C_) g_wqkv[i] = __float2half_rn(in_w[i]);
        if (i < C_ * C_)     g_wout[i] = __float2half_rn(out_w[i]);
    }
}

// ---------------- 2) SE gate MLP -----------------------------------------------
__global__ void se_kernel(const float* __restrict__ w1, const float* __restrict__ b1,
                          const float* __restrict__ w2, const float* __restrict__ b2) {
    __shared__ float h1s[B_ * CR_];
    int tid = threadIdx.x;
    {
        int b = tid >> 6, j = tid & 63;
        float s = b1[j];
        const float* pw = w1 + j * C_;
        const float* pp = g_pooled + b * C_;
        for (int c = 0; c < C_; c++) s += pp[c] * pw[c];
        h1s[tid] = fmaxf(s, 0.f);
    }
    __syncthreads();
    for (int i = tid; i < B_ * C_; i += 512) {
        int b = i >> 8, c = i & 255;
        float s = b2[c];
        const float* pw = w2 + c * CR_;
        const float* ph = h1s + b * CR_;
        for (int j = 0; j < CR_; j++) s += ph[j] * pw[j];
        g_ca[i] = 1.0f / (1.0f + expf(-s));
    }
}

// ---------------- 3) gather gated windows into fp16 token matrix ---------------
__global__ void gather_kernel(const float* __restrict__ x) {
    int hp = blockIdx.x;
    int cg = blockIdx.y;
    int b  = blockIdx.z;
    __shared__ float tile[32][65];
    int tid = threadIdx.x;
    int wp = tid & 63, ci = tid >> 6;
    const float* base = x + (((size_t)(b * C_ + cg * 32)) << 12) + hp * W_;
#pragma unroll
    for (int i = 0; i < 8; i++) {
        int c = ci + i * 4;
        tile[c][wp] = base[((size_t)c << 12) + wp];
    }
    __syncthreads();
    int j = tid & 31, pi = tid >> 5;
    int hw = hp >> 3, r = hp & 7;
    float cav = g_ca[b * C_ + cg * 32 + j];
#pragma unroll
    for (int i = 0; i < 8; i++) {
        int wpp = pi + i * 8;
        int ww = wpp >> 3, cc = wpp & 7;
        int l = (hw * 8 + ww) * 8 + b;
        int t = l * 64 + (r * 8 + cc);
        g_xw[(size_t)t * C_ + cg * 32 + j] = __float2half_rn(tile[j][wpp] * cav);
    }
}

// -------- shared mainloop: fp16 HMMA GEMM 128x128, cp.async 3-stage (R12) ------
#define STAGE_HALFS (256 * AST)
#define GEMM_SMEM (3 * STAGE_HALFS * 2)

__device__ __forceinline__ void gemm_load_chunk(__half* Ab, __half* Bb,
    const __half* __restrict__ A, const __half* __restrict__ Bm,
    int m0, int n0, int k0, int tid) {
#pragma unroll
    for (int p = 0; p < 2; p++) {
        int i = tid + p * 256;
        int row = i >> 2, q = i & 3;
        cp16(smem_u32(Ab + row * AST + q * 8), A + (size_t)(m0 + row) * C_ + k0 + q * 8);
        cp16(smem_u32(Bb + row * AST + q * 8), Bm + (size_t)(n0 + row) * C_ + k0 + q * 8);
    }
    CP_COMMIT();
}

// 8 warps as 2(M) x 4(N); warp tile 64 x 32; acc[mt 0..3][nt 0..3][4]
__device__ __forceinline__ void gemm_mainloop(__half* gsm,
    const __half* __restrict__ A, const __half* __restrict__ Bm,
    int m0, int n0, float acc[4][4][4]) {
    int tid = threadIdx.x;
    int lane = tid & 31, wid = tid >> 5;
    int wm = wid & 1, wn = wid >> 1;
    int lrow = lane & 15, lkq = lane >> 4;

    __half* Ab[3] = { gsm, gsm + STAGE_HALFS, gsm + 2 * STAGE_HALFS };
#define BB(s) (Ab[s] + 128 * AST)

    gemm_load_chunk(Ab[0], BB(0), A, Bm, m0, n0, 0, tid);
    gemm_load_chunk(Ab[1], BB(1), A, Bm, m0, n0, BK, tid);

    for (int chunk = 0; chunk < 8; chunk++) {
        int buf = chunk - (chunk >= 6 ? 6 : (chunk >= 3 ? 3 : 0));   // chunk % 3
        if (chunk < 7) CP_WAIT1(); else CP_WAIT0();
        __syncthreads();
        if (chunk < 6) {
            int nb = buf + 2 >= 3 ? buf - 1 : buf + 2;               // (chunk+2) % 3
            gemm_load_chunk(Ab[nb], BB(nb), A, Bm, m0, n0, (chunk + 2) * BK, tid);
        }

        uint32_t sA0 = smem_u32(Ab[buf]);
        uint32_t sB0 = smem_u32(BB(buf));
#pragma unroll
        for (int ks = 0; ks < 2; ks++) {
            int kk = ks * 16 + lkq * 8;
            uint32_t a4[4][4], bA[4], bB[4];
#pragma unroll
            for (int mt = 0; mt < 4; mt++) {
                int row = wm * 64 + mt * 16 + lrow;
                ldsm_x4(a4[mt][0], a4[mt][1], a4[mt][2], a4[mt][3],
                        sA0 + (uint32_t)(row * AST + kk) * 2);
            }
            ldsm_x4(bA[0], bA[1], bA[2], bA[3],
                    sB0 + (uint32_t)((wn * 32 + lrow) * AST + kk) * 2);
            ldsm_x4(bB[0], bB[1], bB[2], bB[3],
                    sB0 + (uint32_t)((wn * 32 + 16 + lrow) * AST + kk) * 2);
            uint32_t b0[2] = { bA[0], bA[2] }, b1[2] = { bA[1], bA[3] };
            uint32_t b2[2] = { bB[0], bB[2] }, b3[2] = { bB[1], bB[3] };
#pragma unroll
            for (int mt = 0; mt < 4; mt++) {
                mma_f16(acc[mt][0], a4[mt], b0);
                mma_f16(acc[mt][1], a4[mt], b1);
                mma_f16(acc[mt][2], a4[mt], b2);
                mma_f16(acc[mt][3], a4[mt], b3);
            }
        }
    }
#undef BB
}

// ---------------- 4) QKV projection (fp16 HMMA) --------------------------------
__global__ __launch_bounds__(256, 2) void qkv_mma_kernel(const float* __restrict__ bias) {
    extern __shared__ __half gsm[];
    int m0 = blockIdx.x * 128;
    int n0 = blockIdx.y * 128;
    float acc[4][4][4];
#pragma unroll
    for (int mt = 0; mt < 4; mt++)
#pragma unroll
        for (int nt = 0; nt < 4; nt++)
#pragma unroll
            for (int j = 0; j < 4; j++) acc[mt][nt][j] = 0.f;

    gemm_mainloop(gsm, g_xw, g_wqkv, m0, n0, acc);

    int lane = threadIdx.x & 31, wid = threadIdx.x >> 5;
    int wm = wid & 1, wn = wid >> 1;
    int sec = n0 >> 8;                 // 0=Q, 1=K, 2=V
    __half* dst = (sec == 0) ? g_q : (sec == 1) ? g_k : g_v;
    float scale = (sec == 0) ? QK_SCALE_LOG2 : 1.0f;
    int l = (m0 >> 6) + wm;
    int r = lane >> 2;
#pragma unroll
    for (int mt = 0; mt < 4; mt++) {
#pragma unroll
        for (int nt = 0; nt < 4; nt++) {
            int col = n0 + wn * 32 + nt * 8 + (lane & 3) * 2;
            int oc = col & 255;
            int h = oc >> 5, d = oc & 31;
            float2 bi = *(const float2*)&bias[col];
#pragma unroll
            for (int half = 0; half < 2; half++) {
                int n = mt * 16 + r + half * 8;
                float v0 = (acc[mt][nt][half * 2 + 0] + bi.x) * scale;
                float v1 = (acc[mt][nt][half * 2 + 1] + bi.y) * scale;
                size_t idx = (((size_t)(n * NH_ + h) * L_ + l) << 5) + d;
                *(uint32_t*)(dst + idx) = pkh2(v0, v1);
            }
        }
    }
}

// ---------------- 5) attention: deep asymmetric K/V prefetch -------------------
// K prefetched 3 ahead (ring 3), V 2 ahead (ring 3); per-iter commits: Vg then Kg;
// end-of-iter wait_group 2 leaves the two newest groups in flight.
__device__ __forceinline__ void attn_compute_S(float s[8][4], const uint32_t aq[2][4],
                                               uint32_t sK, int lrow, int lkq) {
#pragma unroll
    for (int j = 0; j < 8; j++)
#pragma unroll
        for (int c = 0; c < 4; c++) s[j][c] = 0.f;
#pragma unroll
    for (int ks = 0; ks < 2; ks++) {
        int kk = ks * 16 + lkq * 8;
#pragma unroll
        for (int j = 0; j < 4; j++) {
            uint32_t b4[4];
            ldsm_x4(b4[0], b4[1], b4[2], b4[3],
                    sK + (uint32_t)((j * 16 + lrow) * AST + kk) * 2);
            uint32_t b0[2] = { b4[0], b4[2] }, b1[2] = { b4[1], b4[3] };
            mma_f16(s[2 * j + 0], aq[ks], b0);
            mma_f16(s[2 * j + 1], aq[ks], b1);
        }
    }
}

__global__ __launch_bounds__(256, 2) void attn_mma_kernel() {
    int qt = blockIdx.x;   // 0..3
    int h  = blockIdx.y;   // 0..7
    int n  = blockIdx.z;   // 0..63
    __shared__ __half Qs[128][AST];
    __shared__ __half Ks[3][64][AST];
    __shared__ __half Vs[3][64][AST];

    size_t head = ((size_t)(n * NH_ + h)) * L_ * HD_;
    const __half* qg = g_q + head;
    const __half* kg = g_k + head;
    const __half* vg = g_v + head;

    int tid = threadIdx.x;
    int lane = tid & 31, wid = tid >> 5;
    int kvrow = tid >> 2, kvq = tid & 3;
    int lrow = lane & 15, lkq = lane >> 4;

    // prologue: P0 = {K0,V0,K1,V1}, P1 = {K2}
    {
        size_t gi0 = (size_t)kvrow * HD_ + kvq * 8;
        size_t gi1 = (size_t)(64 + kvrow) * HD_ + kvq * 8;
        cp16(smem_u32(&Ks[0][kvrow][kvq * 8]), kg + gi0);
        cp16(smem_u32(&Vs[0][kvrow][kvq * 8]), vg + gi0);
        cp16(smem_u32(&Ks[1][kvrow][kvq * 8]), kg + gi1);
        cp16(smem_u32(&Vs[1][kvrow][kvq * 8]), vg + gi1);
        CP_COMMIT();
        cp16(smem_u32(&Ks[2][kvrow][kvq * 8]), kg + (size_t)(128 + kvrow) * HD_ + kvq * 8);
        CP_COMMIT();
    }
#pragma unroll
    for (int p = 0; p < 2; p++) {
        int i = tid + p * 256;
        int row = i >> 2, q = i & 3;
        *(uint4*)&Qs[row][q * 8] = *(const uint4*)(qg + (size_t)(qt * 128 + row) * HD_ + q * 8);
    }
    uint32_t sQ = smem_u32(&Qs[0][0]);

    CP_WAIT1();          // P0 complete; P1 (K2) may fly
    __syncthreads();

    // hoisted persistent Q fragments (warp rows [wid*16, wid*16+16))
    uint32_t aq[2][4];
#pragma unroll
    for (int ks = 0; ks < 2; ks++)
        ldsm_x4(aq[ks][0], aq[ks][1], aq[ks][2], aq[ks][3],
                sQ + (uint32_t)((wid * 16 + lrow) * AST + ks * 16 + lkq * 8) * 2);

    float s[2][8][4];
    attn_compute_S(s[0], aq, smem_u32(&Ks[0][0][0]), lrow, lkq);
    __syncthreads();     // all warps done reading Ks[0] before iter-0 overwrites it

    float o[4][4];
#pragma unroll
    for (int i = 0; i < 4; i++)
#pragma unroll
        for (int j = 0; j < 4; j++) o[i][j] = 0.f;
    float mrow[2] = { -1e30f, -1e30f };
    float lsum[2] = { 0.f, 0.f };

    // ring indices: vread = kt%3, vwrite = (kt+2)%3, kread = (kt+1)%3, kwrite = kt%3
    int vread = 0, vwrite = 2, kread = 1, kwrite = 0;

#pragma unroll 2
    for (int kt = 0; kt < 8; kt++) {
        const int cur = kt & 1, nxt = cur ^ 1;
        // Vg: V(kt+2) -> Vs[vwrite]
        if (kt < 6) {
            cp16(smem_u32(&Vs[vwrite][kvrow][kvq * 8]),
                 vg + (size_t)((kt + 2) * 64 + kvrow) * HD_ + kvq * 8);
            CP_COMMIT();
        }
        // Kg: K(kt+3) -> Ks[kwrite]
        if (kt < 5) {
            cp16(smem_u32(&Ks[kwrite][kvrow][kvq * 8]),
                 kg + (size_t)((kt + 3) * 64 + kvrow) * HD_ + kvq * 8);
            CP_COMMIT();
        }
        // S(kt+1) from Ks[kread] (prefetched >= 1 full iteration ago)
        if (kt < 7)
            attn_compute_S(s[nxt], aq, smem_u32(&Ks[kread][0][0]), lrow, lkq);

        // ---- online softmax on s[cur] -> packed-half P fragments ----
        float (*sc)[4] = s[cur];
        float mx0 = -1e30f, mx1 = -1e30f;
#pragma unroll
        for (int j = 0; j < 8; j++) {
            mx0 = fmaxf(mx0, fmaxf(sc[j][0], sc[j][1]));
            mx1 = fmaxf(mx1, fmaxf(sc[j][2], sc[j][3]));
        }
        mx0 = fmaxf(mx0, __shfl_xor_sync(0xffffffffu, mx0, 1));
        mx0 = fmaxf(mx0, __shfl_xor_sync(0xffffffffu, mx0, 2));
        mx1 = fmaxf(mx1, __shfl_xor_sync(0xffffffffu, mx1, 1));
        mx1 = fmaxf(mx1, __shfl_xor_sync(0xffffffffu, mx1, 2));
        float mn0 = fmaxf(mrow[0], mx0), mn1 = fmaxf(mrow[1], mx1);
        float al0 = ex2(mrow[0] - mn0), al1 = ex2(mrow[1] - mn1);

        uint32_t ap[4][4];
        uint32_t hs0 = 0, hs1 = 0;
#pragma unroll
        for (int ks = 0; ks < 4; ks++) {
            int j0 = 2 * ks, j1 = 2 * ks + 1;
            uint32_t p00 = ex2h2(cvt2h(sc[j0][0] - mn0, sc[j0][1] - mn0));
            uint32_t p01 = ex2h2(cvt2h(sc[j0][2] - mn1, sc[j0][3] - mn1));
            uint32_t p10 = ex2h2(cvt2h(sc[j1][0] - mn0, sc[j1][1] - mn0));
            uint32_t p11 = ex2h2(cvt2h(sc[j1][2] - mn1, sc[j1][3] - mn1));
            ap[ks][0] = p00; ap[ks][1] = p01; ap[ks][2] = p10; ap[ks][3] = p11;
            hs0 = hadd2_(hadd2_(hs0, p00), p10);
            hs1 = hadd2_(hadd2_(hs1, p01), p11);
        }
        {
            float2 f0 = __half22float2(*(const __half2*)&hs0);
            float2 f1 = __half22float2(*(const __half2*)&hs1);
            lsum[0] = lsum[0] * al0 + f0.x + f0.y;
            lsum[1] = lsum[1] * al1 + f1.x + f1.y;
        }
        mrow[0] = mn0; mrow[1] = mn1;
#pragma unroll
        for (int nt = 0; nt < 4; nt++) {
            o[nt][0] *= al0; o[nt][1] *= al0;
            o[nt][2] *= al1; o[nt][3] *= al1;
        }

        // ---- O += P V from Vs[vread] ----
        uint32_t sV = smem_u32(&Vs[vread][0][0]);
#pragma unroll
        for (int ks = 0; ks < 4; ks++) {
#pragma unroll
            for (int half = 0; half < 2; half++) {
                uint32_t v4[4];
                ldsm_x4_t(v4[0], v4[1], v4[2], v4[3],
                          sV + (uint32_t)((ks * 16 + lrow) * AST + half * 16 + lkq * 8) * 2);
                uint32_t bv0[2] = { v4[0], v4[1] }, bv1[2] = { v4[2], v4[3] };
                mma_f16(o[half * 2 + 0], ap[ks], bv0);
                mma_f16(o[half * 2 + 1], ap[ks], bv1);
            }
        }

        // advance rings; allow the two newest groups (V(kt+2), K(kt+3)) to fly
        vread  = (vread  == 2) ? 0 : vread  + 1;
        vwrite = (vwrite == 2) ? 0 : vwrite + 1;
        kread  = (kread  == 2) ? 0 : kread  + 1;
        kwrite = (kwrite == 2) ? 0 : kwrite + 1;
        if (kt < 7) {
            CP_WAIT2();
            __syncthreads();
        }
    }

    // ---- epilogue: final lsum reduction + write ao ----
    lsum[0] += __shfl_xor_sync(0xffffffffu, lsum[0], 1);
    lsum[0] += __shfl_xor_sync(0xffffffffu, lsum[0], 2);
    lsum[1] += __shfl_xor_sync(0xffffffffu, lsum[1], 1);
    lsum[1] += __shfl_xor_sync(0xffffffffu, lsum[1], 2);
    int r = lane >> 2, cp = (lane & 3) * 2;
#pragma unroll
    for (int half = 0; half < 2; half++) {
        int row = wid * 16 + r + half * 8;
        int l = qt * 128 + row;
        float inv = 1.0f / lsum[half];
        size_t base = ((size_t)(l * 64 + n)) * C_ + h * 32;
#pragma unroll
        for (int nt = 0; nt < 4; nt++) {
            float v0 = o[nt][half * 2 + 0] * inv;
            float v1 = o[nt][half * 2 + 1] * inv;
            *(uint32_t*)(g_ao + base + nt * 8 + cp) = pkh2(v0, v1);
        }
    }
}

// ---------------- 6) out-proj (fp16 HMMA) + gated residual ---------------------
__global__ __launch_bounds__(256, 2) void outproj_mma_kernel(const float* __restrict__ bias,
                                                             const float* __restrict__ x,
                                                             float* __restrict__ out) {
    extern __shared__ __half gsm[];
    int m0 = blockIdx.x * 128;
    int n0 = blockIdx.y * 128;
    float acc[4][4][4];
#pragma unroll
    for (int mt = 0; mt < 4; mt++)
#pragma unroll
        for (int nt = 0; nt < 4; nt++)
#pragma unroll
            for (int j = 0; j < 4; j++) acc[mt][nt][j] = 0.f;

    gemm_mainloop(gsm, g_ao, g_wout, m0, n0, acc);

    int lane = threadIdx.x & 31, wid = threadIdx.x >> 5;
    int wm = wid & 1, wn = wid >> 1;
    int l = (m0 >> 6) + wm;
    int win = l >> 3, b = l & 7;
    int r = lane >> 2;
#pragma unroll
    for (int mt = 0; mt < 4; mt++) {
#pragma unroll
        for (int nt = 0; nt < 4; nt++) {
            int col = n0 + wn * 32 + nt * 8 + (lane & 3) * 2;
            float2 bi = *(const float2*)&bias[col];
            float ca0 = g_ca[b * C_ + col];
            float ca1 = g_ca[b * C_ + col + 1];
#pragma unroll
            for (int half = 0; half < 2; half++) {
                int wq = mt * 16 + r + half * 8;
                size_t idx0 = (((size_t)(b * C_ + col)) * H_ + win) * W_ + wq;
                size_t idx1 = idx0 + (size_t)H_ * W_;
                out[idx0] = x[idx0] * ca0 + acc[mt][nt][half * 2 + 0] + bi.x;
                out[idx1] = x[idx1] * ca1 + acc[mt][nt][half * 2 + 1] + bi.y;
            }
        }
    }
}

// ---------------- launch --------------------------------------------------------
extern "C" void kernel_launch(void* const* d_in, const int* in_sizes, int n_in,
                              void* d_out, int out_size) {
    const float* x     = (const float*)d_in[0];
    const float* ca_w1 = (const float*)d_in[1];
    const float* ca_b1 = (const float*)d_in[2];
    const float* ca_w2 = (const float*)d_in[3];
    const float* ca_b2 = (const float*)d_in[4];
    const float* in_w  = (const float*)d_in[5];
    const float* in_b  = (const float*)d_in[6];
    const float* out_w = (const float*)d_in[7];
    const float* out_b = (const float*)d_in[8];
    float* out = (float*)d_out;

    cudaFuncSetAttribute(qkv_mma_kernel, cudaFuncAttributeMaxDynamicSharedMemorySize, GEMM_SMEM);
    cudaFuncSetAttribute(outproj_mma_kernel, cudaFuncAttributeMaxDynamicSharedMemorySize, GEMM_SMEM);

    int conv_blocks = (3 * C_ * C_ + 255) / 256;
    prep_kernel<<<B_ * C_ + conv_blocks, 256>>>(x, in_w, out_w);
    se_kernel<<<1, 512>>>(ca_w1, ca_b1, ca_w2, ca_b2);
    gather_kernel<<<dim3(64, 8, 8), 256>>>(x);
    qkv_mma_kernel<<<dim3(NTOK / 128, 6), 256, GEMM_SMEM>>>(in_b);
    attn_mma_kernel<<<dim3(4, 8, 64), 256>>>();
    outproj_mma_kernel<<<dim3(NTOK / 128, 2), 256, GEMM_SMEM>>>(out_b, x, out);
}

// round 15
// speedup vs baseline: 1.0356x; 1.0127x over previous
#include <cuda_runtime.h>
#include <cuda_fp16.h>
#include <cstdint>
#include <math.h>

// Problem constants
#define B_  8
#define C_  256
#define H_  64
#define W_  64
#define CR_ 64
#define L_  512
#define N_  64
#define NH_ 8
#define HD_ 32
#define NTOK (L_ * N_)          // 32768
// 1/sqrt(32) * log2(e): softmax runs in the exp2 domain
#define QK_SCALE_LOG2 (0.17677669529663687f * 1.44269504088896341f)

// ---------------- scratch (device globals; no allocations allowed) -------------
__device__ float g_pooled[B_ * C_];
__device__ float g_ca[B_ * C_];
__device__ __align__(16) __half g_xw[NTOK * C_];      // gated tokens [t][c]
__device__ __align__(16) __half g_wqkv[3 * C_ * C_];
__device__ __align__(16) __half g_wout[C_ * C_];
__device__ __align__(16) __half g_q[N_ * NH_ * L_ * HD_];  // scale*log2e folded
__device__ __align__(16) __half g_k[N_ * NH_ * L_ * HD_];
__device__ __align__(16) __half g_v[N_ * NH_ * L_ * HD_];
__device__ __align__(16) __half g_ao[NTOK * C_];      // attn out [t][h*32+d]

// ---------------- PTX helpers ---------------------------------------------------
__device__ __forceinline__ uint32_t smem_u32(const void* p) {
    uint32_t a;
    asm("{ .reg .u64 t; cvta.to.shared.u64 t, %1; cvt.u32.u64 %0, t; }" : "=r"(a) : "l"(p));
    return a;
}
__device__ __forceinline__ void ldsm_x4(uint32_t& r0, uint32_t& r1, uint32_t& r2, uint32_t& r3,
                                        uint32_t addr) {
    asm volatile("ldmatrix.sync.aligned.m8n8.x4.shared.b16 {%0,%1,%2,%3}, [%4];"
                 : "=r"(r0), "=r"(r1), "=r"(r2), "=r"(r3) : "r"(addr));
}
__device__ __forceinline__ void ldsm_x4_t(uint32_t& r0, uint32_t& r1, uint32_t& r2, uint32_t& r3,
                                          uint32_t addr) {
    asm volatile("ldmatrix.sync.aligned.m8n8.x4.trans.shared.b16 {%0,%1,%2,%3}, [%4];"
                 : "=r"(r0), "=r"(r1), "=r"(r2), "=r"(r3) : "r"(addr));
}
__device__ __forceinline__ void mma_f16(float* c, const uint32_t* a, const uint32_t* b) {
    asm volatile("mma.sync.aligned.m16n8k16.row.col.f32.f16.f16.f32 "
                 "{%0,%1,%2,%3}, {%4,%5,%6,%7}, {%8,%9}, {%0,%1,%2,%3};"
                 : "+f"(c[0]), "+f"(c[1]), "+f"(c[2]), "+f"(c[3])
                 : "r"(a[0]), "r"(a[1]), "r"(a[2]), "r"(a[3]), "r"(b[0]), "r"(b[1]));
}
__device__ __forceinline__ void cp16(uint32_t saddr, const void* g) {
    asm volatile("cp.async.cg.shared.global [%0], [%1], 16;" :: "r"(saddr), "l"(g));
}
#define CP_COMMIT() asm volatile("cp.async.commit_group;" ::: "memory")
#define CP_WAIT0()  asm volatile("cp.async.wait_group 0;" ::: "memory")
#define CP_WAIT1()  asm volatile("cp.async.wait_group 1;" ::: "memory")

#define BK 32
#define AST 40   // padded smem row stride in halfs (80B: conflict-free ldmatrix)

// f32 exp2 on MUFU
__device__ __forceinline__ float ex2(float x) {
    float r;
    asm("ex2.approx.f32 %0, %1;" : "=f"(r) : "f"(x));
    return r;
}
// packed half2 exp2 on MUFU
__device__ __forceinline__ uint32_t ex2h2(uint32_t x) {
    uint32_t r;
    asm("ex2.approx.f16x2 %0, %1;" : "=r"(r) : "r"(x));
    return r;
}
__device__ __forceinline__ uint32_t cvt2h(float lo, float hi) {
    uint32_t d;
    asm("cvt.rn.f16x2.f32 %0, %1, %2;" : "=r"(d) : "f"(hi), "f"(lo));
    return d;
}
__device__ __forceinline__ uint32_t hadd2_(uint32_t a, uint32_t b) {
    uint32_t d;
    asm("add.rn.f16x2 %0, %1, %2;" : "=r"(d) : "r"(a), "r"(b));
    return d;
}
__device__ __forceinline__ uint32_t pkh2(float a, float b) {
    __half2 t = __floats2half2_rn(a, b);
    return *reinterpret_cast<uint32_t*>(&t);
}

// ---------------- 1) merged prep: pool (blocks 0..2047) + W convert -------------
__global__ void prep_kernel(const float* __restrict__ x,
                            const float* __restrict__ in_w, const float* __restrict__ out_w) {
    int bid = blockIdx.x;
    if (bid < B_ * C_) {
        const float* p = x + (size_t)bid * (H_ * W_);
        float s = 0.f;
        for (int i = threadIdx.x; i < H_ * W_; i += 256) s += p[i];
        __shared__ float red[8];
        for (int o = 16; o; o >>= 1) s += __shfl_xor_sync(0xffffffffu, s, o);
        if ((threadIdx.x & 31) == 0) red[threadIdx.x >> 5] = s;
        __syncthreads();
        if (threadIdx.x < 8) {
            s = red[threadIdx.x];
            for (int o = 4; o; o >>= 1) s += __shfl_xor_sync(0xffu, s, o);
            if (threadIdx.x == 0) g_pooled[bid] = s * (1.0f / (H_ * W_));
        }
    } else {
        int i = (bid - B_ * C_) * 256 + threadIdx.x;
        if (i < 3 * C_ * C_) g_wqkv[i] = __float2half_rn(in_w[i]);
        if (i < C_ * C_)     g_wout[i] = __float2half_rn(out_w[i]);
    }
}

// ---------------- 2) SE gate MLP -----------------------------------------------
__global__ void se_kernel(const float* __restrict__ w1, const float* __restrict__ b1,
                          const float* __restrict__ w2, const float* __restrict__ b2) {
    __shared__ float h1s[B_ * CR_];
    int tid = threadIdx.x;
    {
        int b = tid >> 6, j = tid & 63;
        float s = b1[j];
        const float* pw = w1 + j * C_;
        const float* pp = g_pooled + b * C_;
        for (int c = 0; c < C_; c++) s += pp[c] * pw[c];
        h1s[tid] = fmaxf(s, 0.f);
    }
    __syncthreads();
    for (int i = tid; i < B_ * C_; i += 512) {
        int b = i >> 8, c = i & 255;
        float s = b2[c];
        const float* pw = w2 + c * CR_;
        const float* ph = h1s + b * CR_;
        for (int j = 0; j < CR_; j++) s += ph[j] * pw[j];
        g_ca[i] = 1.0f / (1.0f + expf(-s));
    }
}

// ---------------- 3) gather gated windows into fp16 token matrix ---------------
__global__ void gather_kernel(const float* __restrict__ x) {
    int hp = blockIdx.x;
    int cg = blockIdx.y;
    int b  = blockIdx.z;
    __shared__ float tile[32][65];
    int tid = threadIdx.x;
    int wp = tid & 63, ci = tid >> 6;
    const float* base = x + (((size_t)(b * C_ + cg * 32)) << 12) + hp * W_;
#pragma unroll
    for (int i = 0; i < 8; i++) {
        int c = ci + i * 4;
        tile[c][wp] = base[((size_t)c << 12) + wp];
    }
    __syncthreads();
    int j = tid & 31, pi = tid >> 5;
    int hw = hp >> 3, r = hp & 7;
    float cav = g_ca[b * C_ + cg * 32 + j];
#pragma unroll
    for (int i = 0; i < 8; i++) {
        int wpp = pi + i * 8;
        int ww = wpp >> 3, cc = wpp & 7;
        int l = (hw * 8 + ww) * 8 + b;
        int t = l * 64 + (r * 8 + cc);
        g_xw[(size_t)t * C_ + cg * 32 + j] = __float2half_rn(tile[j][wpp] * cav);
    }
}

// -------- shared mainloop: fp16 HMMA GEMM 128x128, cp.async 3-stage ------------
#define STAGE_HALFS (256 * AST)
#define GEMM_SMEM (3 * STAGE_HALFS * 2)

__device__ __forceinline__ void gemm_load_chunk(__half* Ab, __half* Bb,
    const __half* __restrict__ A, const __half* __restrict__ Bm,
    int m0, int n0, int k0, int tid) {
#pragma unroll
    for (int p = 0; p < 2; p++) {
        int i = tid + p * 256;
        int row = i >> 2, q = i & 3;
        cp16(smem_u32(Ab + row * AST + q * 8), A + (size_t)(m0 + row) * C_ + k0 + q * 8);
        cp16(smem_u32(Bb + row * AST + q * 8), Bm + (size_t)(n0 + row) * C_ + k0 + q * 8);
    }
    CP_COMMIT();
}

// 8 warps as 2(M) x 4(N); warp tile 64 x 32; acc[mt 0..3][nt 0..3][4]
__device__ __forceinline__ void gemm_mainloop(__half* gsm,
    const __half* __restrict__ A, const __half* __restrict__ Bm,
    int m0, int n0, float acc[4][4][4]) {
    int tid = threadIdx.x;
    int lane = tid & 31, wid = tid >> 5;
    int wm = wid & 1, wn = wid >> 1;
    int lrow = lane & 15, lkq = lane >> 4;

    __half* Ab[3] = { gsm, gsm + STAGE_HALFS, gsm + 2 * STAGE_HALFS };
#define BB(s) (Ab[s] + 128 * AST)

    gemm_load_chunk(Ab[0], BB(0), A, Bm, m0, n0, 0, tid);
    gemm_load_chunk(Ab[1], BB(1), A, Bm, m0, n0, BK, tid);

    for (int chunk = 0; chunk < 8; chunk++) {
        int buf = chunk - (chunk >= 6 ? 6 : (chunk >= 3 ? 3 : 0));   // chunk % 3
        if (chunk < 7) CP_WAIT1(); else CP_WAIT0();
        __syncthreads();
        if (chunk < 6) {
            int nb = buf + 2 >= 3 ? buf - 1 : buf + 2;               // (chunk+2) % 3
            gemm_load_chunk(Ab[nb], BB(nb), A, Bm, m0, n0, (chunk + 2) * BK, tid);
        }

        uint32_t sA0 = smem_u32(Ab[buf]);
        uint32_t sB0 = smem_u32(BB(buf));
#pragma unroll
        for (int ks = 0; ks < 2; ks++) {
            int kk = ks * 16 + lkq * 8;
            uint32_t a4[4][4], bA[4], bB[4];
#pragma unroll
            for (int mt = 0; mt < 4; mt++) {
                int row = wm * 64 + mt * 16 + lrow;
                ldsm_x4(a4[mt][0], a4[mt][1], a4[mt][2], a4[mt][3],
                        sA0 + (uint32_t)(row * AST + kk) * 2);
            }
            ldsm_x4(bA[0], bA[1], bA[2], bA[3],
                    sB0 + (uint32_t)((wn * 32 + lrow) * AST + kk) * 2);
            ldsm_x4(bB[0], bB[1], bB[2], bB[3],
                    sB0 + (uint32_t)((wn * 32 + 16 + lrow) * AST + kk) * 2);
            uint32_t b0[2] = { bA[0], bA[2] }, b1[2] = { bA[1], bA[3] };
            uint32_t b2[2] = { bB[0], bB[2] }, b3[2] = { bB[1], bB[3] };
#pragma unroll
            for (int mt = 0; mt < 4; mt++) {
                mma_f16(acc[mt][0], a4[mt], b0);
                mma_f16(acc[mt][1], a4[mt], b1);
                mma_f16(acc[mt][2], a4[mt], b2);
                mma_f16(acc[mt][3], a4[mt], b3);
            }
        }
    }
#undef BB
}

// ---------------- 4) QKV projection (fp16 HMMA) --------------------------------
__global__ __launch_bounds__(256, 2) void qkv_mma_kernel(const float* __restrict__ bias) {
    extern __shared__ __half gsm[];
    int m0 = blockIdx.x * 128;
    int n0 = blockIdx.y * 128;
    float acc[4][4][4];
#pragma unroll
    for (int mt = 0; mt < 4; mt++)
#pragma unroll
        for (int nt = 0; nt < 4; nt++)
#pragma unroll
            for (int j = 0; j < 4; j++) acc[mt][nt][j] = 0.f;

    gemm_mainloop(gsm, g_xw, g_wqkv, m0, n0, acc);

    int lane = threadIdx.x & 31, wid = threadIdx.x >> 5;
    int wm = wid & 1, wn = wid >> 1;
    int sec = n0 >> 8;                 // 0=Q, 1=K, 2=V
    __half* dst = (sec == 0) ? g_q : (sec == 1) ? g_k : g_v;
    float scale = (sec == 0) ? QK_SCALE_LOG2 : 1.0f;
    int l = (m0 >> 6) + wm;
    int r = lane >> 2;
#pragma unroll
    for (int mt = 0; mt < 4; mt++) {
#pragma unroll
        for (int nt = 0; nt < 4; nt++) {
            int col = n0 + wn * 32 + nt * 8 + (lane & 3) * 2;
            int oc = col & 255;
            int h = oc >> 5, d = oc & 31;
            float2 bi = *(const float2*)&bias[col];
#pragma unroll
            for (int half = 0; half < 2; half++) {
                int n = mt * 16 + r + half * 8;
                float v0 = (acc[mt][nt][half * 2 + 0] + bi.x) * scale;
                float v1 = (acc[mt][nt][half * 2 + 1] + bi.y) * scale;
                size_t idx = (((size_t)(n * NH_ + h) * L_ + l) << 5) + d;
                *(uint32_t*)(dst + idx) = pkh2(v0, v1);
            }
        }
    }
}

// ---------------- 5) attention (fp16 HMMA flash, interleaved softmax/PV) -------
__device__ __forceinline__ void attn_compute_S(float s[8][4], const uint32_t aq[2][4],
                                               uint32_t sK, int lrow, int lkq) {
#pragma unroll
    for (int j = 0; j < 8; j++)
#pragma unroll
        for (int c = 0; c < 4; c++) s[j][c] = 0.f;
#pragma unroll
    for (int ks = 0; ks < 2; ks++) {
        int kk = ks * 16 + lkq * 8;
#pragma unroll
        for (int j = 0; j < 4; j++) {
            uint32_t b4[4];
            ldsm_x4(b4[0], b4[1], b4[2], b4[3],
                    sK + (uint32_t)((j * 16 + lrow) * AST + kk) * 2);
            uint32_t b0[2] = { b4[0], b4[2] }, b1[2] = { b4[1], b4[3] };
            mma_f16(s[2 * j + 0], aq[ks], b0);
            mma_f16(s[2 * j + 1], aq[ks], b1);
        }
    }
}

__global__ __launch_bounds__(256, 2) void attn_mma_kernel() {
    int qt = blockIdx.x;   // 0..3
    int h  = blockIdx.y;   // 0..7
    int n  = blockIdx.z;   // 0..63
    __shared__ __half Qs[128][AST];
    __shared__ __half Ks[2][64][AST];
    __shared__ __half Vs[2][64][AST];

    size_t head = ((size_t)(n * NH_ + h)) * L_ * HD_;
    const __half* qg = g_q + head;
    const __half* kg = g_k + head;
    const __half* vg = g_v + head;

    int tid = threadIdx.x;
    int lane = tid & 31, wid = tid >> 5;
    int kvrow = tid >> 2, kvq = tid & 3;
    int lrow = lane & 15, lkq = lane >> 4;

    // prologue: K0+V0 (group), K1 (group), Q plain
    {
        size_t gi = (size_t)kvrow * HD_ + kvq * 8;
        cp16(smem_u32(&Ks[0][kvrow][kvq * 8]), kg + gi);
        cp16(smem_u32(&Vs[0][kvrow][kvq * 8]), vg + gi);
        CP_COMMIT();
        cp16(smem_u32(&Ks[1][kvrow][kvq * 8]), kg + (size_t)(64 + kvrow) * HD_ + kvq * 8);
        CP_COMMIT();
    }
#pragma unroll
    for (int p = 0; p < 2; p++) {
        int i = tid + p * 256;
        int row = i >> 2, q = i & 3;
        *(uint4*)&Qs[row][q * 8] = *(const uint4*)(qg + (size_t)(qt * 128 + row) * HD_ + q * 8);
    }
    uint32_t sQ = smem_u32(&Qs[0][0]);

    CP_WAIT0();
    __syncthreads();

    // hoisted persistent Q fragments (warp rows [wid*16, wid*16+16))
    uint32_t aq[2][4];
#pragma unroll
    for (int ks = 0; ks < 2; ks++)
        ldsm_x4(aq[ks][0], aq[ks][1], aq[ks][2], aq[ks][3],
                sQ + (uint32_t)((wid * 16 + lrow) * AST + ks * 16 + lkq * 8) * 2);

    float s[2][8][4];
    attn_compute_S(s[0], aq, smem_u32(&Ks[0][0][0]), lrow, lkq);
    __syncthreads();   // protect Ks[0] from kt=0's K2 prefetch overwrite

    float o[4][4];
#pragma unroll
    for (int i = 0; i < 4; i++)
#pragma unroll
        for (int j = 0; j < 4; j++) o[i][j] = 0.f;
    float mrow[2] = { -1e30f, -1e30f };
    float lsum[2] = { 0.f, 0.f };

#pragma unroll 2
    for (int kt = 0; kt < 8; kt++) {
        const int cur = kt & 1, nxt = cur ^ 1;
        // prefetch K(kt+2) -> Ks[cur] (K(kt) is dead), V(kt+1) -> Vs[nxt]
        if (kt < 6)
            cp16(smem_u32(&Ks[cur][kvrow][kvq * 8]),
                 kg + (size_t)((kt + 2) * 64 + kvrow) * HD_ + kvq * 8);
        if (kt < 7) {
            cp16(smem_u32(&Vs[nxt][kvrow][kvq * 8]),
                 vg + (size_t)((kt + 1) * 64 + kvrow) * HD_ + kvq * 8);
            CP_COMMIT();
            // S(kt+1): independent MMA stream
            attn_compute_S(s[nxt], aq, smem_u32(&Ks[nxt][0][0]), lrow, lkq);
        }

        // ---- online softmax max phase on s[cur] ----
        float (*sc)[4] = s[cur];
        float mx0 = -1e30f, mx1 = -1e30f;
#pragma unroll
        for (int j = 0; j < 8; j++) {
            mx0 = fmaxf(mx0, fmaxf(sc[j][0], sc[j][1]));
            mx1 = fmaxf(mx1, fmaxf(sc[j][2], sc[j][3]));
        }
        mx0 = fmaxf(mx0, __shfl_xor_sync(0xffffffffu, mx0, 1));
        mx0 = fmaxf(mx0, __shfl_xor_sync(0xffffffffu, mx0, 2));
        mx1 = fmaxf(mx1, __shfl_xor_sync(0xffffffffu, mx1, 1));
        mx1 = fmaxf(mx1, __shfl_xor_sync(0xffffffffu, mx1, 2));
        float mn0 = fmaxf(mrow[0], mx0), mn1 = fmaxf(mrow[1], mx1);
        float al0 = ex2(mrow[0] - mn0), al1 = ex2(mrow[1] - mn1);
        mrow[0] = mn0; mrow[1] = mn1;
#pragma unroll
        for (int nt = 0; nt < 4; nt++) {
            o[nt][0] *= al0; o[nt][1] *= al0;
            o[nt][2] *= al1; o[nt][3] *= al1;
        }

        // ---- interleaved exp + PV: per ks, {4 ex2h2 -> 2 ldsm -> 4 MMA} ----
        // spreads MUFU work across the PV tensor phase instead of a burst
        uint32_t sV = smem_u32(&Vs[cur][0][0]);
        uint32_t hs0 = 0, hs1 = 0;
#pragma unroll
        for (int ks = 0; ks < 4; ks++) {
            int j0 = 2 * ks, j1 = 2 * ks + 1;
            uint32_t ap[4];
            ap[0] = ex2h2(cvt2h(sc[j0][0] - mn0, sc[j0][1] - mn0));
            ap[1] = ex2h2(cvt2h(sc[j0][2] - mn1, sc[j0][3] - mn1));
            ap[2] = ex2h2(cvt2h(sc[j1][0] - mn0, sc[j1][1] - mn0));
            ap[3] = ex2h2(cvt2h(sc[j1][2] - mn1, sc[j1][3] - mn1));
            hs0 = hadd2_(hadd2_(hs0, ap[0]), ap[2]);
            hs1 = hadd2_(hadd2_(hs1, ap[1]), ap[3]);
#pragma unroll
            for (int half = 0; half < 2; half++) {
                uint32_t v4[4];
                ldsm_x4_t(v4[0], v4[1], v4[2], v4[3],
                          sV + (uint32_t)((ks * 16 + lrow) * AST + half * 16 + lkq * 8) * 2);
                uint32_t bv0[2] = { v4[0], v4[1] }, bv1[2] = { v4[2], v4[3] };
                mma_f16(o[half * 2 + 0], ap, bv0);
                mma_f16(o[half * 2 + 1], ap, bv1);
            }
        }
        {
            float2 f0 = __half22float2(*(const __half2*)&hs0);
            float2 f1 = __half22float2(*(const __half2*)&hs1);
            lsum[0] = lsum[0] * al0 + f0.x + f0.y;
            lsum[1] = lsum[1] * al1 + f1.x + f1.y;
        }
        if (kt < 7) {
            CP_WAIT0();
            __syncthreads();
        }
    }

    // ---- epilogue: final lsum reduction + write ao ----
    lsum[0] += __shfl_xor_sync(0xffffffffu, lsum[0], 1);
    lsum[0] += __shfl_xor_sync(0xffffffffu, lsum[0], 2);
    lsum[1] += __shfl_xor_sync(0xffffffffu, lsum[1], 1);
    lsum[1] += __shfl_xor_sync(0xffffffffu, lsum[1], 2);
    int r = lane >> 2, cp = (lane & 3) * 2;
#pragma unroll
    for (int half = 0; half < 2; half++) {
        int row = wid * 16 + r + half * 8;
        int l = qt * 128 + row;
        float inv = 1.0f / lsum[half];
        size_t base = ((size_t)(l * 64 + n)) * C_ + h * 32;
#pragma unroll
        for (int nt = 0; nt < 4; nt++) {
            float v0 = o[nt][half * 2 + 0] * inv;
            float v1 = o[nt][half * 2 + 1] * inv;
            *(uint32_t*)(g_ao + base + nt * 8 + cp) = pkh2(v0, v1);
        }
    }
}

// ---------------- 6) out-proj (fp16 HMMA) + gated residual ---------------------
__global__ __launch_bounds__(256, 2) void outproj_mma_kernel(const float* __restrict__ bias,
                                                             const float* __restrict__ x,
                                                             float* __restrict__ out) {
    extern __shared__ __half gsm[];
    int m0 = blockIdx.x * 128;
    int n0 = blockIdx.y * 128;
    float acc[4][4][4];
#pragma unroll
    for (int mt = 0; mt < 4; mt++)
#pragma unroll
        for (int nt = 0; nt < 4; nt++)
#pragma unroll
            for (int j = 0; j < 4; j++) acc[mt][nt][j] = 0.f;

    gemm_mainloop(gsm, g_ao, g_wout, m0, n0, acc);

    int lane = threadIdx.x & 31, wid = threadIdx.x >> 5;
    int wm = wid & 1, wn = wid >> 1;
    int l = (m0 >> 6) + wm;
    int win = l >> 3, b = l & 7;
    int r = lane >> 2;
#pragma unroll
    for (int mt = 0; mt < 4; mt++) {
#pragma unroll
        for (int nt = 0; nt < 4; nt++) {
            int col = n0 + wn * 32 + nt * 8 + (lane & 3) * 2;
            float2 bi = *(const float2*)&bias[col];
            float ca0 = g_ca[b * C_ + col];
            float ca1 = g_ca[b * C_ + col + 1];
#pragma unroll
            for (int half = 0; half < 2; half++) {
                int wq = mt * 16 + r + half * 8;
                size_t idx0 = (((size_t)(b * C_ + col)) * H_ + win) * W_ + wq;
                size_t idx1 = idx0 + (size_t)H_ * W_;
                out[idx0] = x[idx0] * ca0 + acc[mt][nt][half * 2 + 0] + bi.x;
                out[idx1] = x[idx1] * ca1 + acc[mt][nt][half * 2 + 1] + bi.y;
            }
        }
    }
}

// ---------------- launch --------------------------------------------------------
extern "C" void kernel_launch(void* const* d_in, const int* in_sizes, int n_in,
                              void* d_out, int out_size) {
    const float* x     = (const float*)d_in[0];
    const float* ca_w1 = (const float*)d_in[1];
    const float* ca_b1 = (const float*)d_in[2];
    const float* ca_w2 = (const float*)d_in[3];
    const float* ca_b2 = (const float*)d_in[4];
    const float* in_w  = (const float*)d_in[5];
    const float* in_b  = (const float*)d_in[6];
    const float* out_w = (const float*)d_in[7];
    const float* out_b = (const float*)d_in[8];
    float* out = (float*)d_out;

    cudaFuncSetAttribute(qkv_mma_kernel, cudaFuncAttributeMaxDynamicSharedMemorySize, GEMM_SMEM);
    cudaFuncSetAttribute(outproj_mma_kernel, cudaFuncAttributeMaxDynamicSharedMemorySize, GEMM_SMEM);

    int conv_blocks = (3 * C_ * C_ + 255) / 256;
    prep_kernel<<<B_ * C_ + conv_blocks, 256>>>(x, in_w, out_w);
    se_kernel<<<1, 512>>>(ca_w1, ca_b1, ca_w2, ca_b2);
    gather_kernel<<<dim3(64, 8, 8), 256>>>(x);
    qkv_mma_kernel<<<dim3(NTOK / 128, 6), 256, GEMM_SMEM>>>(in_b);
    attn_mma_kernel<<<dim3(4, 8, 64), 256>>>();
    outproj_mma_kernel<<<dim3(NTOK / 128, 2), 256, GEMM_SMEM>>>(out_b, x, out);
}

// round 16
// speedup vs baseline: 1.5372x; 1.4844x over previous
#include <cuda_runtime.h>
#include <cuda_fp16.h>
#include <cstdint>
#include <math.h>

// Problem constants
#define B_  8
#define C_  256
#define H_  64
#define W_  64
#define CR_ 64
#define L_  512
#define N_  64
#define NH_ 8
#define HD_ 32
#define NTOK (L_ * N_)          // 32768
// 1/sqrt(32) * log2(e): softmax runs in the exp2 domain
#define QK_SCALE_LOG2 (0.17677669529663687f * 1.44269504088896341f)

// ---------------- scratch (device globals; no allocations allowed) -------------
__device__ float g_pooled[B_ * C_];
__device__ float g_ca[B_ * C_];
__device__ int   g_cnt[B_];     // zero-init; self-resetting last-block-out counters
__device__ __align__(16) __half g_xw[NTOK * C_];      // gated tokens [t][c]
__device__ __align__(16) __half g_wqkv[3 * C_ * C_];
__device__ __align__(16) __half g_wout[C_ * C_];
__device__ __align__(16) __half g_q[N_ * NH_ * L_ * HD_];  // scale*log2e folded
__device__ __align__(16) __half g_k[N_ * NH_ * L_ * HD_];
__device__ __align__(16) __half g_v[N_ * NH_ * L_ * HD_];
__device__ __align__(16) __half g_ao[NTOK * C_];      // attn out [t][h*32+d]

// ---------------- PTX helpers ---------------------------------------------------
__device__ __forceinline__ uint32_t smem_u32(const void* p) {
    uint32_t a;
    asm("{ .reg .u64 t; cvta.to.shared.u64 t, %1; cvt.u32.u64 %0, t; }" : "=r"(a) : "l"(p));
    return a;
}
__device__ __forceinline__ void ldsm_x4(uint32_t& r0, uint32_t& r1, uint32_t& r2, uint32_t& r3,
                                        uint32_t addr) {
    asm volatile("ldmatrix.sync.aligned.m8n8.x4.shared.b16 {%0,%1,%2,%3}, [%4];"
                 : "=r"(r0), "=r"(r1), "=r"(r2), "=r"(r3) : "r"(addr));
}
__device__ __forceinline__ void ldsm_x4_t(uint32_t& r0, uint32_t& r1, uint32_t& r2, uint32_t& r3,
                                          uint32_t addr) {
    asm volatile("ldmatrix.sync.aligned.m8n8.x4.trans.shared.b16 {%0,%1,%2,%3}, [%4];"
                 : "=r"(r0), "=r"(r1), "=r"(r2), "=r"(r3) : "r"(addr));
}
__device__ __forceinline__ void mma_f16(float* c, const uint32_t* a, const uint32_t* b) {
    asm volatile("mma.sync.aligned.m16n8k16.row.col.f32.f16.f16.f32 "
                 "{%0,%1,%2,%3}, {%4,%5,%6,%7}, {%8,%9}, {%0,%1,%2,%3};"
                 : "+f"(c[0]), "+f"(c[1]), "+f"(c[2]), "+f"(c[3])
                 : "r"(a[0]), "r"(a[1]), "r"(a[2]), "r"(a[3]), "r"(b[0]), "r"(b[1]));
}
__device__ __forceinline__ void cp16(uint32_t saddr, const void* g) {
    asm volatile("cp.async.cg.shared.global [%0], [%1], 16;" :: "r"(saddr), "l"(g));
}
#define CP_COMMIT() asm volatile("cp.async.commit_group;" ::: "memory")
#define CP_WAIT0()  asm volatile("cp.async.wait_group 0;" ::: "memory")
#define CP_WAIT1()  asm volatile("cp.async.wait_group 1;" ::: "memory")

#define BK 32
#define AST 40   // padded smem row stride in halfs (80B: conflict-free ldmatrix)

// f32 exp2 on MUFU
__device__ __forceinline__ float ex2(float x) {
    float r;
    asm("ex2.approx.f32 %0, %1;" : "=f"(r) : "f"(x));
    return r;
}
// packed half2 exp2 on MUFU
__device__ __forceinline__ uint32_t ex2h2(uint32_t x) {
    uint32_t r;
    asm("ex2.approx.f16x2 %0, %1;" : "=r"(r) : "r"(x));
    return r;
}
__device__ __forceinline__ uint32_t cvt2h(float lo, float hi) {
    uint32_t d;
    asm("cvt.rn.f16x2.f32 %0, %1, %2;" : "=r"(d) : "f"(hi), "f"(lo));
    return d;
}
__device__ __forceinline__ uint32_t hadd2_(uint32_t a, uint32_t b) {
    uint32_t d;
    asm("add.rn.f16x2 %0, %1, %2;" : "=r"(d) : "r"(a), "r"(b));
    return d;
}
__device__ __forceinline__ uint32_t pkh2(float a, float b) {
    __half2 t = __floats2half2_rn(a, b);
    return *reinterpret_cast<uint32_t*>(&t);
}

// ---------------- 1) merged prep: pool + SE (last-block-out) + W convert --------
__global__ void prep_kernel(const float* __restrict__ x,
                            const float* __restrict__ in_w, const float* __restrict__ out_w,
                            const float* __restrict__ w1, const float* __restrict__ b1,
                            const float* __restrict__ w2, const float* __restrict__ b2) {
    int bid = blockIdx.x;
    if (bid < B_ * C_) {
        int b = bid >> 8;
        const float* p = x + (size_t)bid * (H_ * W_);
        float s = 0.f;
        for (int i = threadIdx.x; i < H_ * W_; i += 256) s += p[i];
        __shared__ float red[8];
        __shared__ int lastf;
        for (int o = 16; o; o >>= 1) s += __shfl_xor_sync(0xffffffffu, s, o);
        if ((threadIdx.x & 31) == 0) red[threadIdx.x >> 5] = s;
        __syncthreads();
        if (threadIdx.x == 0) {
            float t = 0.f;
#pragma unroll
            for (int i = 0; i < 8; i++) t += red[i];
            g_pooled[bid] = t * (1.0f / (H_ * W_));
            __threadfence();
            int old = atomicAdd(&g_cnt[b], 1);
            lastf = (old == C_ - 1);
        }
        __syncthreads();
        if (lastf) {
            // this is the last pool block for batch b: compute the SE gate here
            __shared__ float pl[C_];
            __shared__ float h1s[CR_];
            for (int i = threadIdx.x; i < C_; i += 256) pl[i] = g_pooled[b * C_ + i];
            __syncthreads();
            if (threadIdx.x < CR_) {
                float t = b1[threadIdx.x];
                const float* pw = w1 + threadIdx.x * C_;
                for (int c = 0; c < C_; c++) t += pl[c] * pw[c];
                h1s[threadIdx.x] = fmaxf(t, 0.f);
            }
            __syncthreads();
            {
                float t = b2[threadIdx.x];
                const float* pw = w2 + threadIdx.x * CR_;
                for (int k = 0; k < CR_; k++) t += h1s[k] * pw[k];
                g_ca[b * C_ + threadIdx.x] = 1.0f / (1.0f + expf(-t));
            }
            if (threadIdx.x == 0) g_cnt[b] = 0;   // reset for next graph replay
        }
    } else {
        int i = (bid - B_ * C_) * 256 + threadIdx.x;
        if (i < 3 * C_ * C_) g_wqkv[i] = __float2half_rn(in_w[i]);
        if (i < C_ * C_)     g_wout[i] = __float2half_rn(out_w[i]);
    }
}

// ---------------- 2) gather gated windows into fp16 token matrix ---------------
__global__ void gather_kernel(const float* __restrict__ x) {
    int hp = blockIdx.x;
    int cg = blockIdx.y;
    int b  = blockIdx.z;
    __shared__ float tile[32][65];
    int tid = threadIdx.x;
    int wp = tid & 63, ci = tid >> 6;
    const float* base = x + (((size_t)(b * C_ + cg * 32)) << 12) + hp * W_;
#pragma unroll
    for (int i = 0; i < 8; i++) {
        int c = ci + i * 4;
        tile[c][wp] = base[((size_t)c << 12) + wp];
    }
    __syncthreads();
    int j = tid & 31, pi = tid >> 5;
    int hw = hp >> 3, r = hp & 7;
    float cav = g_ca[b * C_ + cg * 32 + j];
#pragma unroll
    for (int i = 0; i < 8; i++) {
        int wpp = pi + i * 8;
        int ww = wpp >> 3, cc = wpp & 7;
        int l = (hw * 8 + ww) * 8 + b;
        int t = l * 64 + (r * 8 + cc);
        g_xw[(size_t)t * C_ + cg * 32 + j] = __float2half_rn(tile[j][wpp] * cav);
    }
}

// -------- shared mainloop: fp16 HMMA GEMM 128x128, cp.async 3-stage ------------
#define STAGE_HALFS (256 * AST)
#define GEMM_SMEM (3 * STAGE_HALFS * 2)

__device__ __forceinline__ void gemm_load_chunk(__half* Ab, __half* Bb,
    const __half* __restrict__ A, const __half* __restrict__ Bm,
    int m0, int n0, int k0, int tid) {
#pragma unroll
    for (int p = 0; p < 2; p++) {
        int i = tid + p * 256;
        int row = i >> 2, q = i & 3;
        cp16(smem_u32(Ab + row * AST + q * 8), A + (size_t)(m0 + row) * C_ + k0 + q * 8);
        cp16(smem_u32(Bb + row * AST + q * 8), Bm + (size_t)(n0 + row) * C_ + k0 + q * 8);
    }
    CP_COMMIT();
}

// 8 warps as 2(M) x 4(N); warp tile 64 x 32; acc[mt 0..3][nt 0..3][4]
__device__ __forceinline__ void gemm_mainloop(__half* gsm,
    const __half* __restrict__ A, const __half* __restrict__ Bm,
    int m0, int n0, float acc[4][4][4]) {
    int tid = threadIdx.x;
    int lane = tid & 31, wid = tid >> 5;
    int wm = wid & 1, wn = wid >> 1;
    int lrow = lane & 15, lkq = lane >> 4;

    __half* Ab[3] = { gsm, gsm + STAGE_HALFS, gsm + 2 * STAGE_HALFS };
#define BB(s) (Ab[s] + 128 * AST)

    gemm_load_chunk(Ab[0], BB(0), A, Bm, m0, n0, 0, tid);
    gemm_load_chunk(Ab[1], BB(1), A, Bm, m0, n0, BK, tid);

    for (int chunk = 0; chunk < 8; chunk++) {
        int buf = chunk - (chunk >= 6 ? 6 : (chunk >= 3 ? 3 : 0));   // chunk % 3
        if (chunk < 7) CP_WAIT1(); else CP_WAIT0();
        __syncthreads();
        if (chunk < 6) {
            int nb = buf + 2 >= 3 ? buf - 1 : buf + 2;               // (chunk+2) % 3
            gemm_load_chunk(Ab[nb], BB(nb), A, Bm, m0, n0, (chunk + 2) * BK, tid);
        }

        uint32_t sA0 = smem_u32(Ab[buf]);
        uint32_t sB0 = smem_u32(BB(buf));
#pragma unroll
        for (int ks = 0; ks < 2; ks++) {
            int kk = ks * 16 + lkq * 8;
            uint32_t a4[4][4], bA[4], bB[4];
#pragma unroll
            for (int mt = 0; mt < 4; mt++) {
                int row = wm * 64 + mt * 16 + lrow;
                ldsm_x4(a4[mt][0], a4[mt][1], a4[mt][2], a4[mt][3],
                        sA0 + (uint32_t)(row * AST + kk) * 2);
            }
            ldsm_x4(bA[0], bA[1], bA[2], bA[3],
                    sB0 + (uint32_t)((wn * 32 + lrow) * AST + kk) * 2);
            ldsm_x4(bB[0], bB[1], bB[2], bB[3],
                    sB0 + (uint32_t)((wn * 32 + 16 + lrow) * AST + kk) * 2);
            uint32_t b0[2] = { bA[0], bA[2] }, b1[2] = { bA[1], bA[3] };
            uint32_t b2[2] = { bB[0], bB[2] }, b3[2] = { bB[1], bB[3] };
#pragma unroll
            for (int mt = 0; mt < 4; mt++) {
                mma_f16(acc[mt][0], a4[mt], b0);
                mma_f16(acc[mt][1], a4[mt], b1);
                mma_f16(acc[mt][2], a4[mt], b2);
                mma_f16(acc[mt][3], a4[mt], b3);
            }
        }
    }
#undef BB
}

// ---------------- 3) QKV projection (fp16 HMMA) --------------------------------
__global__ __launch_bounds__(256, 2) void qkv_mma_kernel(const float* __restrict__ bias) {
    extern __shared__ __half gsm[];
    int m0 = blockIdx.x * 128;
    int n0 = blockIdx.y * 128;
    float acc[4][4][4];
#pragma unroll
    for (int mt = 0; mt < 4; mt++)
#pragma unroll
        for (int nt = 0; nt < 4; nt++)
#pragma unroll
            for (int j = 0; j < 4; j++) acc[mt][nt][j] = 0.f;

    gemm_mainloop(gsm, g_xw, g_wqkv, m0, n0, acc);

    int lane = threadIdx.x & 31, wid = threadIdx.x >> 5;
    int wm = wid & 1, wn = wid >> 1;
    int sec = n0 >> 8;                 // 0=Q, 1=K, 2=V
    __half* dst = (sec == 0) ? g_q : (sec == 1) ? g_k : g_v;
    float scale = (sec == 0) ? QK_SCALE_LOG2 : 1.0f;
    int l = (m0 >> 6) + wm;
    int r = lane >> 2;
#pragma unroll
    for (int mt = 0; mt < 4; mt++) {
#pragma unroll
        for (int nt = 0; nt < 4; nt++) {
            int col = n0 + wn * 32 + nt * 8 + (lane & 3) * 2;
            int oc = col & 255;
            int h = oc >> 5, d = oc & 31;
            float2 bi = *(const float2*)&bias[col];
#pragma unroll
            for (int half = 0; half < 2; half++) {
                int n = mt * 16 + r + half * 8;
                float v0 = (acc[mt][nt][half * 2 + 0] + bi.x) * scale;
                float v1 = (acc[mt][nt][half * 2 + 1] + bi.y) * scale;
                size_t idx = (((size_t)(n * NH_ + h) * L_ + l) << 5) + d;
                *(uint32_t*)(dst + idx) = pkh2(v0, v1);
            }
        }
    }
}

// ---------------- 4) attention (fp16 HMMA flash, interleaved softmax/PV) -------
__device__ __forceinline__ void attn_compute_S(float s[8][4], const uint32_t aq[2][4],
                                               uint32_t sK, int lrow, int lkq) {
#pragma unroll
    for (int j = 0; j < 8; j++)
#pragma unroll
        for (int c = 0; c < 4; c++) s[j][c] = 0.f;
#pragma unroll
    for (int ks = 0; ks < 2; ks++) {
        int kk = ks * 16 + lkq * 8;
#pragma unroll
        for (int j = 0; j < 4; j++) {
            uint32_t b4[4];
            ldsm_x4(b4[0], b4[1], b4[2], b4[3],
                    sK + (uint32_t)((j * 16 + lrow) * AST + kk) * 2);
            uint32_t b0[2] = { b4[0], b4[2] }, b1[2] = { b4[1], b4[3] };
            mma_f16(s[2 * j + 0], aq[ks], b0);
            mma_f16(s[2 * j + 1], aq[ks], b1);
        }
    }
}

__global__ __launch_bounds__(256, 2) void attn_mma_kernel() {
    int qt = blockIdx.x;   // 0..3
    int h  = blockIdx.y;   // 0..7
    int n  = blockIdx.z;   // 0..63
    __shared__ __half Qs[128][AST];
    __shared__ __half Ks[2][64][AST];
    __shared__ __half Vs[2][64][AST];

    size_t head = ((size_t)(n * NH_ + h)) * L_ * HD_;
    const __half* qg = g_q + head;
    const __half* kg = g_k + head;
    const __half* vg = g_v + head;

    int tid = threadIdx.x;
    int lane = tid & 31, wid = tid >> 5;
    int kvrow = tid >> 2, kvq = tid & 3;
    int lrow = lane & 15, lkq = lane >> 4;

    // prologue: K0+V0 (group), K1 (group), Q plain
    {
        size_t gi = (size_t)kvrow * HD_ + kvq * 8;
        cp16(smem_u32(&Ks[0][kvrow][kvq * 8]), kg + gi);
        cp16(smem_u32(&Vs[0][kvrow][kvq * 8]), vg + gi);
        CP_COMMIT();
        cp16(smem_u32(&Ks[1][kvrow][kvq * 8]), kg + (size_t)(64 + kvrow) * HD_ + kvq * 8);
        CP_COMMIT();
    }
#pragma unroll
    for (int p = 0; p < 2; p++) {
        int i = tid + p * 256;
        int row = i >> 2, q = i & 3;
        *(uint4*)&Qs[row][q * 8] = *(const uint4*)(qg + (size_t)(qt * 128 + row) * HD_ + q * 8);
    }
    uint32_t sQ = smem_u32(&Qs[0][0]);

    CP_WAIT0();
    __syncthreads();

    // hoisted persistent Q fragments (warp rows [wid*16, wid*16+16))
    uint32_t aq[2][4];
#pragma unroll
    for (int ks = 0; ks < 2; ks++)
        ldsm_x4(aq[ks][0], aq[ks][1], aq[ks][2], aq[ks][3],
                sQ + (uint32_t)((wid * 16 + lrow) * AST + ks * 16 + lkq * 8) * 2);

    float s[2][8][4];
    attn_compute_S(s[0], aq, smem_u32(&Ks[0][0][0]), lrow, lkq);
    __syncthreads();   // protect Ks[0] from kt=0's K2 prefetch overwrite

    float o[4][4];
#pragma unroll
    for (int i = 0; i < 4; i++)
#pragma unroll
        for (int j = 0; j < 4; j++) o[i][j] = 0.f;
    float mrow[2] = { -1e30f, -1e30f };
    float lsum[2] = { 0.f, 0.f };

#pragma unroll 2
    for (int kt = 0; kt < 8; kt++) {
        const int cur = kt & 1, nxt = cur ^ 1;
        // prefetch K(kt+2) -> Ks[cur] (K(kt) is dead), V(kt+1) -> Vs[nxt]
        if (kt < 6)
            cp16(smem_u32(&Ks[cur][kvrow][kvq * 8]),
                 kg + (size_t)((kt + 2) * 64 + kvrow) * HD_ + kvq * 8);
        if (kt < 7) {
            cp16(smem_u32(&Vs[nxt][kvrow][kvq * 8]),
                 vg + (size_t)((kt + 1) * 64 + kvrow) * HD_ + kvq * 8);
            CP_COMMIT();
            // S(kt+1): independent MMA stream
            attn_compute_S(s[nxt], aq, smem_u32(&Ks[nxt][0][0]), lrow, lkq);
        }

        // ---- online softmax max phase on s[cur] ----
        float (*sc)[4] = s[cur];
        float mx0 = -1e30f, mx1 = -1e30f;
#pragma unroll
        for (int j = 0; j < 8; j++) {
            mx0 = fmaxf(mx0, fmaxf(sc[j][0], sc[j][1]));
            mx1 = fmaxf(mx1, fmaxf(sc[j][2], sc[j][3]));
        }
        mx0 = fmaxf(mx0, __shfl_xor_sync(0xffffffffu, mx0, 1));
        mx0 = fmaxf(mx0, __shfl_xor_sync(0xffffffffu, mx0, 2));
        mx1 = fmaxf(mx1, __shfl_xor_sync(0xffffffffu, mx1, 1));
        mx1 = fmaxf(mx1, __shfl_xor_sync(0xffffffffu, mx1, 2));
        float mn0 = fmaxf(mrow[0], mx0), mn1 = fmaxf(mrow[1], mx1);
        float al0 = ex2(mrow[0] - mn0), al1 = ex2(mrow[1] - mn1);
        mrow[0] = mn0; mrow[1] = mn1;
#pragma unroll
        for (int nt = 0; nt < 4; nt++) {
            o[nt][0] *= al0; o[nt][1] *= al0;
            o[nt][2] *= al1; o[nt][3] *= al1;
        }

        // ---- interleaved exp + PV: per ks, {4 ex2h2 -> 2 ldsm -> 4 MMA} ----
        uint32_t sV = smem_u32(&Vs[cur][0][0]);
        uint32_t hs0 = 0, hs1 = 0;
#pragma unroll
        for (int ks = 0; ks < 4; ks++) {
            int j0 = 2 * ks, j1 = 2 * ks + 1;
            uint32_t ap[4];
            ap[0] = ex2h2(cvt2h(sc[j0][0] - mn0, sc[j0][1] - mn0));
            ap[1] = ex2h2(cvt2h(sc[j0][2] - mn1, sc[j0][3] - mn1));
            ap[2] = ex2h2(cvt2h(sc[j1][0] - mn0, sc[j1][1] - mn0));
            ap[3] = ex2h2(cvt2h(sc[j1][2] - mn1, sc[j1][3] - mn1));
            hs0 = hadd2_(hadd2_(hs0, ap[0]), ap[2]);
            hs1 = hadd2_(hadd2_(hs1, ap[1]), ap[3]);
#pragma unroll
            for (int half = 0; half < 2; half++) {
                uint32_t v4[4];
                ldsm_x4_t(v4[0], v4[1], v4[2], v4[3],
                          sV + (uint32_t)((ks * 16 + lrow) * AST + half * 16 + lkq * 8) * 2);
                uint32_t bv0[2] = { v4[0], v4[1] }, bv1[2] = { v4[2], v4[3] };
                mma_f16(o[half * 2 + 0], ap, bv0);
                mma_f16(o[half * 2 + 1], ap, bv1);
            }
        }
        {
            float2 f0 = __half22float2(*(const __half2*)&hs0);
            float2 f1 = __half22float2(*(const __half2*)&hs1);
            lsum[0] = lsum[0] * al0 + f0.x + f0.y;
            lsum[1] = lsum[1] * al1 + f1.x + f1.y;
        }
        if (kt < 7) {
            CP_WAIT0();
            __syncthreads();
        }
    }

    // ---- epilogue: final lsum reduction + write ao ----
    lsum[0] += __shfl_xor_sync(0xffffffffu, lsum[0], 1);
    lsum[0] += __shfl_xor_sync(0xffffffffu, lsum[0], 2);
    lsum[1] += __shfl_xor_sync(0xffffffffu, lsum[1], 1);
    lsum[1] += __shfl_xor_sync(0xffffffffu, lsum[1], 2);
    int r = lane >> 2, cp = (lane & 3) * 2;
#pragma unroll
    for (int half = 0; half < 2; half++) {
        int row = wid * 16 + r + half * 8;
        int l = qt * 128 + row;
        float inv = 1.0f / lsum[half];
        size_t base = ((size_t)(l * 64 + n)) * C_ + h * 32;
#pragma unroll
        for (int nt = 0; nt < 4; nt++) {
            float v0 = o[nt][half * 2 + 0] * inv;
            float v1 = o[nt][half * 2 + 1] * inv;
            *(uint32_t*)(g_ao + base + nt * 8 + cp) = pkh2(v0, v1);
        }
    }
}

// ---------------- 5) out-proj (fp16 HMMA) + gated residual ---------------------
__global__ __launch_bounds__(256, 2) void outproj_mma_kernel(const float* __restrict__ bias,
                                                             const float* __restrict__ x,
                                                             float* __restrict__ out) {
    extern __shared__ __half gsm[];
    int m0 = blockIdx.x * 128;
    int n0 = blockIdx.y * 128;
    float acc[4][4][4];
#pragma unroll
    for (int mt = 0; mt < 4; mt++)
#pragma unroll
        for (int nt = 0; nt < 4; nt++)
#pragma unroll
            for (int j = 0; j < 4; j++) acc[mt][nt][j] = 0.f;

    gemm_mainloop(gsm, g_ao, g_wout, m0, n0, acc);

    int lane = threadIdx.x & 31, wid = threadIdx.x >> 5;
    int wm = wid & 1, wn = wid >> 1;
    int l = (m0 >> 6) + wm;
    int win = l >> 3, b = l & 7;
    int r = lane >> 2;
#pragma unroll
    for (int mt = 0; mt < 4; mt++) {
#pragma unroll
        for (int nt = 0; nt < 4; nt++) {
            int col = n0 + wn * 32 + nt * 8 + (lane & 3) * 2;
            float2 bi = *(const float2*)&bias[col];
            float ca0 = g_ca[b * C_ + col];
            float ca1 = g_ca[b * C_ + col + 1];
#pragma unroll
            for (int half = 0; half < 2; half++) {
                int wq = mt * 16 + r + half * 8;
                size_t idx0 = (((size_t)(b * C_ + col)) * H_ + win) * W_ + wq;
                size_t idx1 = idx0 + (size_t)H_ * W_;
                out[idx0] = x[idx0] * ca0 + acc[mt][nt][half * 2 + 0] + bi.x;
                out[idx1] = x[idx1] * ca1 + acc[mt][nt][half * 2 + 1] + bi.y;
            }
        }
    }
}

// ---------------- launch --------------------------------------------------------
extern "C" void kernel_launch(void* const* d_in, const int* in_sizes, int n_in,
                              void* d_out, int out_size) {
    const float* x     = (const float*)d_in[0];
    const float* ca_w1 = (const float*)d_in[1];
    const float* ca_b1 = (const float*)d_in[2];
    const float* ca_w2 = (const float*)d_in[3];
    const float* ca_b2 = (const float*)d_in[4];
    const float* in_w  = (const float*)d_in[5];
    const float* in_b  = (const float*)d_in[6];
    const float* out_w = (const float*)d_in[7];
    const float* out_b = (const float*)d_in[8];
    float* out = (float*)d_out;

    cudaFuncSetAttribute(qkv_mma_kernel, cudaFuncAttributeMaxDynamicSharedMemorySize, GEMM_SMEM);
    cudaFuncSetAttribute(outproj_mma_kernel, cudaFuncAttributeMaxDynamicSharedMemorySize, GEMM_SMEM);

    int conv_blocks = (3 * C_ * C_ + 255) / 256;
    prep_kernel<<<B_ * C_ + conv_blocks, 256>>>(x, in_w, out_w, ca_w1, ca_b1, ca_w2, ca_b2);
    gather_kernel<<<dim3(64, 8, 8), 256>>>(x);
    qkv_mma_kernel<<<dim3(NTOK / 128, 6), 256, GEMM_SMEM>>>(in_b);
    attn_mma_kernel<<<dim3(4, 8, 64), 256>>>();       // launch index 3 -> ncu capture slot
    outproj_mma_kernel<<<dim3(NTOK / 128, 2), 256, GEMM_SMEM>>>(out_b, x, out);
}